// round 1
// baseline (speedup 1.0000x reference)
#include <cuda_runtime.h>
#include <cuda_bf16.h>
#include <cstdint>

// ---------------- Problem constants ----------------
#define BATCH   8
#define HRES    256
#define WRES    256
#define CDIM    96
#define HEADS   6
#define HD      16
#define WS      8
#define NTOK    64              // tokens per window (WS*WS)
#define SHIFT   4
#define NWIN_SIDE 32            // 256/8
#define NWIN    (BATCH * NWIN_SIDE * NWIN_SIDE)   // 8192
#define TOKENS  (BATCH * HRES * WRES)             // 524288

// ---------------- Scratch (device globals, no allocation) ----------------
__device__ float g_qkv[(size_t)TOKENS * 288];   // 604 MB
__device__ float g_o  [(size_t)TOKENS * 96];    // 201 MB
__device__ float g_x1 [(size_t)TOKENS * 96];    // 201 MB

// Map window-token (tw = win*64 + p) -> source pixel linear index in x
__device__ __forceinline__ int token_to_pixel(int tw) {
    int win = tw >> 6, p = tw & 63;
    int b  = win >> 10;
    int rem = win & 1023;
    int wh = rem >> 5, ww = rem & 31;
    int hh = (wh << 3) + (p >> 3);
    int wp = (ww << 3) + (p & 7);
    int sh = (hh + SHIFT) & 255;
    int sw = (wp + SHIFT) & 255;
    return (b << 16) | (sh << 8) | sw;
}

// =======================================================================
// Kernel 1: LN1 + shifted-window gather + QKV GEMM (K=96, N=288)
// grid: TOKENS/32 blocks, 288 threads
// =======================================================================
__global__ __launch_bounds__(288) void qkv_kernel(
    const float* __restrict__ x, const float* __restrict__ lng,
    const float* __restrict__ lnb, const float* __restrict__ W,
    const float* __restrict__ bias)
{
    __shared__ float s_in[32][97];
    const int tid  = threadIdx.x;
    const int tok0 = blockIdx.x * 32;

    // gather 32 rows of x (with shift/window permutation)
    for (int l = tid; l < 32 * 96; l += 288) {
        int t = l / 96, k = l - t * 96;
        int gidx = token_to_pixel(tok0 + t);
        s_in[t][k] = x[(size_t)gidx * 96 + k];
    }
    __syncthreads();

    // LayerNorm (warp per token)
    const int warp = tid >> 5, lane = tid & 31;
    for (int t = warp; t < 32; t += 9) {
        float v0 = s_in[t][lane], v1 = s_in[t][lane + 32], v2 = s_in[t][lane + 64];
        float s = v0 + v1 + v2;
        float q = v0 * v0 + v1 * v1 + v2 * v2;
        #pragma unroll
        for (int o = 16; o; o >>= 1) {
            s += __shfl_xor_sync(0xffffffffu, s, o);
            q += __shfl_xor_sync(0xffffffffu, q, o);
        }
        float mu  = s * (1.0f / 96.0f);
        float var = q * (1.0f / 96.0f) - mu * mu;
        float rs  = rsqrtf(var + 1e-5f);
        s_in[t][lane]      = (v0 - mu) * rs * lng[lane]      + lnb[lane];
        s_in[t][lane + 32] = (v1 - mu) * rs * lng[lane + 32] + lnb[lane + 32];
        s_in[t][lane + 64] = (v2 - mu) * rs * lng[lane + 64] + lnb[lane + 64];
    }
    __syncthreads();

    // GEMM: each thread owns column j, 32 token rows
    const int j = tid;
    float acc[32];
    #pragma unroll
    for (int t = 0; t < 32; ++t) acc[t] = 0.0f;
    #pragma unroll 4
    for (int k = 0; k < 96; ++k) {
        float w = W[k * 288 + j];
        #pragma unroll
        for (int t = 0; t < 32; ++t) acc[t] += s_in[t][k] * w;
    }
    const float bj = bias[j];
    #pragma unroll
    for (int t = 0; t < 32; ++t)
        g_qkv[(size_t)(tok0 + t) * 288 + j] = acc[t] + bj;
}

// =======================================================================
// Kernel 2: windowed attention. grid (NWIN, HEADS), 128 threads.
// =======================================================================
__global__ __launch_bounds__(128) void attn_kernel(const float* __restrict__ rpbt)
{
    __shared__ float s_q[64][17], s_k[64][17], s_v[64][17];
    __shared__ float s_att[64][65];
    __shared__ int   s_reg[64];

    const int win = blockIdx.x;
    const int h   = blockIdx.y;
    const int tid = threadIdx.x;
    const int tokbase = win << 6;

    // stage q,k,v head slices
    for (int l = tid; l < 3 * 64 * 16; l += 128) {
        int mat = l >> 10;
        int rem = l & 1023;
        int row = rem >> 4, col = rem & 15;
        float v = g_qkv[(size_t)(tokbase + row) * 288 + mat * 96 + h * 16 + col];
        if (mat == 0)      s_q[row][col] = v * 0.25f;   // hd^-0.5
        else if (mat == 1) s_k[row][col] = v;
        else               s_v[row][col] = v;
    }
    // shift-mask region ids (post-shift coordinates)
    if (tid < 64) {
        int rem = win & 1023;
        int wh = rem >> 5, ww = rem & 31;
        int hh = (wh << 3) + (tid >> 3);
        int wp = (ww << 3) + (tid & 7);
        int rh = (hh < 248) ? 0 : ((hh < 252) ? 1 : 2);
        int rw = (wp < 248) ? 0 : ((wp < 252) ? 1 : 2);
        s_reg[tid] = rh * 3 + rw;
    }
    __syncthreads();

    // logits + bias + mask
    #pragma unroll
    for (int r = 0; r < 32; ++r) {
        int e = tid + 128 * r;
        int i = e >> 6, jj = e & 63;
        float a = 0.0f;
        #pragma unroll
        for (int d = 0; d < 16; ++d) a += s_q[i][d] * s_k[jj][d];
        int idx = ((i >> 3) - (jj >> 3) + 7) * 15 + ((i & 7) - (jj & 7) + 7);
        a += rpbt[idx * 6 + h];
        if (s_reg[i] != s_reg[jj]) a -= 100.0f;
        s_att[i][jj] = a;
    }
    __syncthreads();

    // softmax: warp per row
    const int warp = tid >> 5, lane = tid & 31;
    for (int rr = 0; rr < 16; ++rr) {
        int i = warp + 4 * rr;
        float a0 = s_att[i][lane], a1 = s_att[i][lane + 32];
        float m = fmaxf(a0, a1);
        #pragma unroll
        for (int o = 16; o; o >>= 1) m = fmaxf(m, __shfl_xor_sync(0xffffffffu, m, o));
        float e0 = __expf(a0 - m), e1 = __expf(a1 - m);
        float s = e0 + e1;
        #pragma unroll
        for (int o = 16; o; o >>= 1) s += __shfl_xor_sync(0xffffffffu, s, o);
        float inv = 1.0f / s;
        s_att[i][lane]      = e0 * inv;
        s_att[i][lane + 32] = e1 * inv;
    }
    __syncthreads();

    // o = att @ v
    #pragma unroll
    for (int r = 0; r < 8; ++r) {
        int e = tid + 128 * r;
        int i = e >> 4, d = e & 15;
        float a = 0.0f;
        #pragma unroll
        for (int jj = 0; jj < 64; ++jj) a += s_att[i][jj] * s_v[jj][d];
        g_o[(size_t)(tokbase + i) * 96 + h * 16 + d] = a;
    }
}

// =======================================================================
// Kernel 3: proj GEMM (96x96) + window-reverse/unshift scatter + residual
// grid: TOKENS/32 blocks, 384 threads (4 groups x 96 columns)
// =======================================================================
__global__ __launch_bounds__(384) void proj_kernel(
    const float* __restrict__ W, const float* __restrict__ bias,
    const float* __restrict__ x)
{
    __shared__ float s_in[32][97];
    const int tid  = threadIdx.x;
    const int tok0 = blockIdx.x * 32;

    for (int l = tid; l < 32 * 96; l += 384) {
        int t = l / 96, k = l - t * 96;
        s_in[t][k] = g_o[(size_t)(tok0 + t) * 96 + k];
    }
    __syncthreads();

    const int j = tid % 96, grp = tid / 96;
    const int t0 = grp * 8;
    float acc[8];
    #pragma unroll
    for (int t = 0; t < 8; ++t) acc[t] = 0.0f;
    #pragma unroll 4
    for (int k = 0; k < 96; ++k) {
        float w = W[k * 96 + j];
        #pragma unroll
        for (int t = 0; t < 8; ++t) acc[t] += s_in[t0 + t][k] * w;
    }
    const float bj = bias[j];
    #pragma unroll
    for (int t = 0; t < 8; ++t) {
        int tw = tok0 + t0 + t;
        size_t gi = (size_t)token_to_pixel(tw) * 96 + j;
        g_x1[gi] = x[gi] + acc[t] + bj;
    }
}

// =======================================================================
// Kernel 4: LN2 + MLP1(96->384) + gelu + MLP2(384->96) + residual, fused
// grid: TOKENS/16 blocks, 384 threads
// =======================================================================
__global__ __launch_bounds__(384) void mlp_kernel(
    const float* __restrict__ lng, const float* __restrict__ lnb,
    const float* __restrict__ W1, const float* __restrict__ b1,
    const float* __restrict__ W2, const float* __restrict__ b2,
    float* __restrict__ out)
{
    __shared__ float s_raw[16][97];
    __shared__ float s_ln [16][96];
    __shared__ float s_hid[16][384];
    const int tid  = threadIdx.x;
    const int tok0 = blockIdx.x * 16;

    for (int l = tid; l < 16 * 96; l += 384) {
        int t = l / 96, k = l - t * 96;
        s_raw[t][k] = g_x1[(size_t)(tok0 + t) * 96 + k];
    }
    __syncthreads();

    const int warp = tid >> 5, lane = tid & 31;
    for (int t = warp; t < 16; t += 12) {
        float v0 = s_raw[t][lane], v1 = s_raw[t][lane + 32], v2 = s_raw[t][lane + 64];
        float s = v0 + v1 + v2;
        float q = v0 * v0 + v1 * v1 + v2 * v2;
        #pragma unroll
        for (int o = 16; o; o >>= 1) {
            s += __shfl_xor_sync(0xffffffffu, s, o);
            q += __shfl_xor_sync(0xffffffffu, q, o);
        }
        float mu  = s * (1.0f / 96.0f);
        float var = q * (1.0f / 96.0f) - mu * mu;
        float rs  = rsqrtf(var + 1e-5f);
        s_ln[t][lane]      = (v0 - mu) * rs * lng[lane]      + lnb[lane];
        s_ln[t][lane + 32] = (v1 - mu) * rs * lng[lane + 32] + lnb[lane + 32];
        s_ln[t][lane + 64] = (v2 - mu) * rs * lng[lane + 64] + lnb[lane + 64];
    }
    __syncthreads();

    // MLP1 + gelu (tanh approximation, matching jax.nn.gelu default)
    {
        const int j = tid;
        float acc[16];
        #pragma unroll
        for (int t = 0; t < 16; ++t) acc[t] = 0.0f;
        #pragma unroll 4
        for (int k = 0; k < 96; ++k) {
            float w = W1[k * 384 + j];
            #pragma unroll
            for (int t = 0; t < 16; ++t) acc[t] += s_ln[t][k] * w;
        }
        const float bj = b1[j];
        #pragma unroll
        for (int t = 0; t < 16; ++t) {
            float v = acc[t] + bj;
            float inner = 0.7978845608028654f * (v + 0.044715f * v * v * v);
            s_hid[t][tid] = 0.5f * v * (1.0f + tanhf(inner));
        }
    }
    __syncthreads();

    // MLP2 + residual
    {
        const int j  = tid % 96, grp = tid / 96;
        const int t0 = grp * 4;
        float acc[4];
        #pragma unroll
        for (int t = 0; t < 4; ++t) acc[t] = 0.0f;
        #pragma unroll 4
        for (int k = 0; k < 384; ++k) {
            float w = W2[k * 96 + j];
            #pragma unroll
            for (int t = 0; t < 4; ++t) acc[t] += s_hid[t0 + t][k] * w;
        }
        const float bj = b2[j];
        #pragma unroll
        for (int t = 0; t < 4; ++t)
            out[(size_t)(tok0 + t0 + t) * 96 + j] = s_raw[t0 + t][j] + acc[t] + bj;
    }
}

// =======================================================================
extern "C" void kernel_launch(void* const* d_in, const int* in_sizes, int n_in,
                              void* d_out, int out_size)
{
    const float* x         = (const float*)d_in[0];
    const float* ln1_scale = (const float*)d_in[1];
    const float* ln1_bias  = (const float*)d_in[2];
    const float* qkv_w     = (const float*)d_in[3];
    const float* qkv_b     = (const float*)d_in[4];
    const float* rpbt      = (const float*)d_in[5];
    const float* proj_w    = (const float*)d_in[6];
    const float* proj_b    = (const float*)d_in[7];
    const float* ln2_scale = (const float*)d_in[8];
    const float* ln2_bias  = (const float*)d_in[9];
    const float* mlp_w1    = (const float*)d_in[10];
    const float* mlp_b1    = (const float*)d_in[11];
    const float* mlp_w2    = (const float*)d_in[12];
    const float* mlp_b2    = (const float*)d_in[13];
    float* out = (float*)d_out;

    qkv_kernel<<<TOKENS / 32, 288>>>(x, ln1_scale, ln1_bias, qkv_w, qkv_b);
    attn_kernel<<<dim3(NWIN, HEADS), 128>>>(rpbt);
    proj_kernel<<<TOKENS / 32, 384>>>(proj_w, proj_b, x);
    mlp_kernel<<<TOKENS / 16, 384>>>(ln2_scale, ln2_bias, mlp_w1, mlp_b1,
                                     mlp_w2, mlp_b2, out);
}

// round 2
// speedup vs baseline: 1.2475x; 1.2475x over previous
#include <cuda_runtime.h>
#include <cuda_bf16.h>
#include <cstdint>

// ---------------- Problem constants ----------------
#define BATCH   8
#define HRES    256
#define WRES    256
#define CDIM    96
#define HEADS   6
#define HD      16
#define WS      8
#define NTOK    64
#define SHIFT   4
#define NWIN_SIDE 32
#define NWIN    (BATCH * NWIN_SIDE * NWIN_SIDE)   // 8192
#define TOKENS  (BATCH * HRES * WRES)             // 524288

// ---------------- Scratch ----------------
__device__ float g_qkv[(size_t)TOKENS * 288];
__device__ float g_o  [(size_t)TOKENS * 96];
__device__ float g_x1 [(size_t)TOKENS * 96];

__device__ __forceinline__ int token_to_pixel(int tw) {
    int win = tw >> 6, p = tw & 63;
    int b  = win >> 10;
    int rem = win & 1023;
    int wh = rem >> 5, ww = rem & 31;
    int hh = (wh << 3) + (p >> 3);
    int wp = (ww << 3) + (p & 7);
    int sh = (hh + SHIFT) & 255;
    int sw = (wp + SHIFT) & 255;
    return (b << 16) | (sh << 8) | sw;
}

// =======================================================================
// Kernel 1: LN1 + shifted-window gather + QKV GEMM (K=96, N=288)
// =======================================================================
__global__ __launch_bounds__(288) void qkv_kernel(
    const float* __restrict__ x, const float* __restrict__ lng,
    const float* __restrict__ lnb, const float* __restrict__ W,
    const float* __restrict__ bias)
{
    __shared__ float s_in[32][100];   // stride 100 floats = 400B (16B aligned)
    const int tid  = threadIdx.x;
    const int tok0 = blockIdx.x * 32;

    // gather (float4)
    for (int l = tid; l < 32 * 24; l += 288) {
        int t = l / 24, k4 = l - t * 24;
        int gidx = token_to_pixel(tok0 + t);
        float4 v = *(const float4*)&x[(size_t)gidx * 96 + k4 * 4];
        *(float4*)&s_in[t][k4 * 4] = v;
    }
    __syncthreads();

    // LayerNorm (warp per token)
    const int warp = tid >> 5, lane = tid & 31;
    for (int t = warp; t < 32; t += 9) {
        float v0 = s_in[t][lane], v1 = s_in[t][lane + 32], v2 = s_in[t][lane + 64];
        float s = v0 + v1 + v2;
        float q = v0 * v0 + v1 * v1 + v2 * v2;
        #pragma unroll
        for (int o = 16; o; o >>= 1) {
            s += __shfl_xor_sync(0xffffffffu, s, o);
            q += __shfl_xor_sync(0xffffffffu, q, o);
        }
        float mu  = s * (1.0f / 96.0f);
        float var = q * (1.0f / 96.0f) - mu * mu;
        float rs  = rsqrtf(var + 1e-5f);
        s_in[t][lane]      = (v0 - mu) * rs * lng[lane]      + lnb[lane];
        s_in[t][lane + 32] = (v1 - mu) * rs * lng[lane + 32] + lnb[lane + 32];
        s_in[t][lane + 64] = (v2 - mu) * rs * lng[lane + 64] + lnb[lane + 64];
    }
    __syncthreads();

    // GEMM: thread owns column j; float4 broadcast reads
    const int j = tid;
    float acc[32];
    #pragma unroll
    for (int t = 0; t < 32; ++t) acc[t] = 0.0f;
    for (int k = 0; k < 96; k += 4) {
        float w0 = W[(k + 0) * 288 + j];
        float w1 = W[(k + 1) * 288 + j];
        float w2 = W[(k + 2) * 288 + j];
        float w3 = W[(k + 3) * 288 + j];
        #pragma unroll
        for (int t = 0; t < 32; ++t) {
            float4 a = *(const float4*)&s_in[t][k];
            acc[t] += a.x * w0 + a.y * w1 + a.z * w2 + a.w * w3;
        }
    }
    const float bj = bias[j];
    #pragma unroll
    for (int t = 0; t < 32; ++t)
        g_qkv[(size_t)(tok0 + t) * 288 + j] = acc[t] + bj;
}

// =======================================================================
// Kernel 2: windowed attention. grid (NWIN, HEADS), 128 threads.
// =======================================================================
__global__ __launch_bounds__(128) void attn_kernel(const float* __restrict__ rpbt)
{
    __shared__ float s_q[64][20], s_k[64][20], s_v[64][20];  // 20 floats = 80B stride
    __shared__ float s_att[64][68];                          // 272B stride
    __shared__ int   s_reg[64];

    const int win = blockIdx.x;
    const int h   = blockIdx.y;
    const int tid = threadIdx.x;
    const int tokbase = win << 6;

    // stage q,k,v head slices (float4: 16 floats = 4 vec per row)
    for (int l = tid; l < 3 * 64 * 4; l += 128) {
        int mat = l >> 8;
        int rem = l & 255;
        int row = rem >> 2, c4 = rem & 3;
        float4 v = *(const float4*)&g_qkv[(size_t)(tokbase + row) * 288 + mat * 96 + h * 16 + c4 * 4];
        if (mat == 0) {
            v.x *= 0.25f; v.y *= 0.25f; v.z *= 0.25f; v.w *= 0.25f;
            *(float4*)&s_q[row][c4 * 4] = v;
        } else if (mat == 1) *(float4*)&s_k[row][c4 * 4] = v;
        else                 *(float4*)&s_v[row][c4 * 4] = v;
    }
    if (tid < 64) {
        int rem = win & 1023;
        int wh = rem >> 5, ww = rem & 31;
        int hh = (wh << 3) + (tid >> 3);
        int wp = (ww << 3) + (tid & 7);
        int rh = (hh < 248) ? 0 : ((hh < 252) ? 1 : 2);
        int rw = (wp < 248) ? 0 : ((wp < 252) ? 1 : 2);
        s_reg[tid] = rh * 3 + rw;
    }
    __syncthreads();

    // logits: thread = (row i = tid/2, half = tid%2), q row in registers
    const int i    = tid >> 1;
    const int half = tid & 1;
    {
        float4 q0 = *(const float4*)&s_q[i][0];
        float4 q1 = *(const float4*)&s_q[i][4];
        float4 q2 = *(const float4*)&s_q[i][8];
        float4 q3 = *(const float4*)&s_q[i][12];
        const int regi = s_reg[i];
        const int ri = i >> 3, ci = i & 7;
        #pragma unroll 4
        for (int jo = 0; jo < 32; ++jo) {
            int jj = half * 32 + jo;
            float4 k0 = *(const float4*)&s_k[jj][0];
            float4 k1 = *(const float4*)&s_k[jj][4];
            float4 k2 = *(const float4*)&s_k[jj][8];
            float4 k3 = *(const float4*)&s_k[jj][12];
            float a = q0.x*k0.x + q0.y*k0.y + q0.z*k0.z + q0.w*k0.w
                    + q1.x*k1.x + q1.y*k1.y + q1.z*k1.z + q1.w*k1.w
                    + q2.x*k2.x + q2.y*k2.y + q2.z*k2.z + q2.w*k2.w
                    + q3.x*k3.x + q3.y*k3.y + q3.z*k3.z + q3.w*k3.w;
            int idx = ((ri - (jj >> 3) + 7) * 15 + (ci - (jj & 7) + 7));
            a += rpbt[idx * 6 + h];
            if (regi != s_reg[jj]) a -= 100.0f;
            s_att[i][jj] = a;
        }
    }
    __syncthreads();

    // softmax: warp per row
    const int warp = tid >> 5, lane = tid & 31;
    for (int rr = 0; rr < 16; ++rr) {
        int r = warp + 4 * rr;
        float a0 = s_att[r][lane], a1 = s_att[r][lane + 32];
        float m = fmaxf(a0, a1);
        #pragma unroll
        for (int o = 16; o; o >>= 1) m = fmaxf(m, __shfl_xor_sync(0xffffffffu, m, o));
        float e0 = __expf(a0 - m), e1 = __expf(a1 - m);
        float s = e0 + e1;
        #pragma unroll
        for (int o = 16; o; o >>= 1) s += __shfl_xor_sync(0xffffffffu, s, o);
        float inv = 1.0f / s;
        s_att[r][lane]      = e0 * inv;
        s_att[r][lane + 32] = e1 * inv;
    }
    __syncthreads();

    // o = att @ v : thread (i, half) owns 8 output dims
    {
        const int d0 = half * 8;
        float acc[8];
        #pragma unroll
        for (int d = 0; d < 8; ++d) acc[d] = 0.0f;
        for (int jj = 0; jj < 64; jj += 4) {
            float4 at = *(const float4*)&s_att[i][jj];
            #pragma unroll
            for (int u = 0; u < 4; ++u) {
                float a = (u == 0) ? at.x : (u == 1) ? at.y : (u == 2) ? at.z : at.w;
                float4 v0 = *(const float4*)&s_v[jj + u][d0];
                float4 v1 = *(const float4*)&s_v[jj + u][d0 + 4];
                acc[0] += a * v0.x; acc[1] += a * v0.y;
                acc[2] += a * v0.z; acc[3] += a * v0.w;
                acc[4] += a * v1.x; acc[5] += a * v1.y;
                acc[6] += a * v1.z; acc[7] += a * v1.w;
            }
        }
        float* dst = &g_o[(size_t)(tokbase + i) * 96 + h * 16 + d0];
        *(float4*)&dst[0] = make_float4(acc[0], acc[1], acc[2], acc[3]);
        *(float4*)&dst[4] = make_float4(acc[4], acc[5], acc[6], acc[7]);
    }
}

// =======================================================================
// Kernel 3: proj GEMM + window-reverse/unshift scatter + residual
// =======================================================================
__global__ __launch_bounds__(384) void proj_kernel(
    const float* __restrict__ W, const float* __restrict__ bias,
    const float* __restrict__ x)
{
    __shared__ float s_in[32][100];
    const int tid  = threadIdx.x;
    const int tok0 = blockIdx.x * 32;

    for (int l = tid; l < 32 * 24; l += 384) {
        int t = l / 24, k4 = l - t * 24;
        float4 v = *(const float4*)&g_o[(size_t)(tok0 + t) * 96 + k4 * 4];
        *(float4*)&s_in[t][k4 * 4] = v;
    }
    __syncthreads();

    const int j = tid % 96, grp = tid / 96;
    const int t0 = grp * 8;
    float acc[8];
    #pragma unroll
    for (int t = 0; t < 8; ++t) acc[t] = 0.0f;
    for (int k = 0; k < 96; k += 4) {
        float w0 = W[(k + 0) * 96 + j];
        float w1 = W[(k + 1) * 96 + j];
        float w2 = W[(k + 2) * 96 + j];
        float w3 = W[(k + 3) * 96 + j];
        #pragma unroll
        for (int t = 0; t < 8; ++t) {
            float4 a = *(const float4*)&s_in[t0 + t][k];
            acc[t] += a.x * w0 + a.y * w1 + a.z * w2 + a.w * w3;
        }
    }
    const float bj = bias[j];
    #pragma unroll
    for (int t = 0; t < 8; ++t) {
        int tw = tok0 + t0 + t;
        size_t gi = (size_t)token_to_pixel(tw) * 96 + j;
        g_x1[gi] = x[gi] + acc[t] + bj;
    }
}

// =======================================================================
// Kernel 4: LN2 + MLP1 + gelu + MLP2 + residual
// =======================================================================
__global__ __launch_bounds__(384) void mlp_kernel(
    const float* __restrict__ lng, const float* __restrict__ lnb,
    const float* __restrict__ W1, const float* __restrict__ b1,
    const float* __restrict__ W2, const float* __restrict__ b2,
    float* __restrict__ out)
{
    __shared__ float s_raw[16][100];
    __shared__ float s_ln [16][96];    // 384B stride, aligned
    __shared__ float s_hid[16][384];
    const int tid  = threadIdx.x;
    const int tok0 = blockIdx.x * 16;

    for (int l = tid; l < 16 * 24; l += 384) {
        int t = l / 24, k4 = l - t * 24;
        float4 v = *(const float4*)&g_x1[(size_t)(tok0 + t) * 96 + k4 * 4];
        *(float4*)&s_raw[t][k4 * 4] = v;
    }
    __syncthreads();

    const int warp = tid >> 5, lane = tid & 31;
    for (int t = warp; t < 16; t += 12) {
        float v0 = s_raw[t][lane], v1 = s_raw[t][lane + 32], v2 = s_raw[t][lane + 64];
        float s = v0 + v1 + v2;
        float q = v0 * v0 + v1 * v1 + v2 * v2;
        #pragma unroll
        for (int o = 16; o; o >>= 1) {
            s += __shfl_xor_sync(0xffffffffu, s, o);
            q += __shfl_xor_sync(0xffffffffu, q, o);
        }
        float mu  = s * (1.0f / 96.0f);
        float var = q * (1.0f / 96.0f) - mu * mu;
        float rs  = rsqrtf(var + 1e-5f);
        s_ln[t][lane]      = (v0 - mu) * rs * lng[lane]      + lnb[lane];
        s_ln[t][lane + 32] = (v1 - mu) * rs * lng[lane + 32] + lnb[lane + 32];
        s_ln[t][lane + 64] = (v2 - mu) * rs * lng[lane + 64] + lnb[lane + 64];
    }
    __syncthreads();

    // MLP1 + gelu
    {
        const int j = tid;
        float acc[16];
        #pragma unroll
        for (int t = 0; t < 16; ++t) acc[t] = 0.0f;
        for (int k = 0; k < 96; k += 4) {
            float w0 = W1[(k + 0) * 384 + j];
            float w1 = W1[(k + 1) * 384 + j];
            float w2 = W1[(k + 2) * 384 + j];
            float w3 = W1[(k + 3) * 384 + j];
            #pragma unroll
            for (int t = 0; t < 16; ++t) {
                float4 a = *(const float4*)&s_ln[t][k];
                acc[t] += a.x * w0 + a.y * w1 + a.z * w2 + a.w * w3;
            }
        }
        const float bj = b1[j];
        #pragma unroll
        for (int t = 0; t < 16; ++t) {
            float v = acc[t] + bj;
            float inner = 0.7978845608028654f * (v + 0.044715f * v * v * v);
            s_hid[t][tid] = 0.5f * v * (1.0f + tanhf(inner));
        }
    }
    __syncthreads();

    // MLP2 + residual
    {
        const int j  = tid % 96, grp = tid / 96;
        const int t0 = grp * 4;
        float acc[4];
        #pragma unroll
        for (int t = 0; t < 4; ++t) acc[t] = 0.0f;
        for (int k = 0; k < 384; k += 4) {
            float w0 = W2[(k + 0) * 96 + j];
            float w1 = W2[(k + 1) * 96 + j];
            float w2 = W2[(k + 2) * 96 + j];
            float w3 = W2[(k + 3) * 96 + j];
            #pragma unroll
            for (int t = 0; t < 4; ++t) {
                float4 a = *(const float4*)&s_hid[t0 + t][k];
                acc[t] += a.x * w0 + a.y * w1 + a.z * w2 + a.w * w3;
            }
        }
        const float bj = b2[j];
        #pragma unroll
        for (int t = 0; t < 4; ++t)
            out[(size_t)(tok0 + t0 + t) * 96 + j] = s_raw[t0 + t][j] + acc[t] + bj;
    }
}

// =======================================================================
extern "C" void kernel_launch(void* const* d_in, const int* in_sizes, int n_in,
                              void* d_out, int out_size)
{
    const float* x         = (const float*)d_in[0];
    const float* ln1_scale = (const float*)d_in[1];
    const float* ln1_bias  = (const float*)d_in[2];
    const float* qkv_w     = (const float*)d_in[3];
    const float* qkv_b     = (const float*)d_in[4];
    const float* rpbt      = (const float*)d_in[5];
    const float* proj_w    = (const float*)d_in[6];
    const float* proj_b    = (const float*)d_in[7];
    const float* ln2_scale = (const float*)d_in[8];
    const float* ln2_bias  = (const float*)d_in[9];
    const float* mlp_w1    = (const float*)d_in[10];
    const float* mlp_b1    = (const float*)d_in[11];
    const float* mlp_w2    = (const float*)d_in[12];
    const float* mlp_b2    = (const float*)d_in[13];
    float* out = (float*)d_out;

    qkv_kernel<<<TOKENS / 32, 288>>>(x, ln1_scale, ln1_bias, qkv_w, qkv_b);
    attn_kernel<<<dim3(NWIN, HEADS), 128>>>(rpbt);
    proj_kernel<<<TOKENS / 32, 384>>>(proj_w, proj_b, x);
    mlp_kernel<<<TOKENS / 16, 384>>>(ln2_scale, ln2_bias, mlp_w1, mlp_b1,
                                     mlp_w2, mlp_b2, out);
}

// round 3
// speedup vs baseline: 1.4505x; 1.1628x over previous
#include <cuda_runtime.h>
#include <cuda_bf16.h>
#include <cstdint>

// ---------------- Problem constants ----------------
#define BATCH   8
#define HRES    256
#define WRES    256
#define CDIM    96
#define HEADS   6
#define WS      8
#define SHIFT   4
#define NWIN    8192
#define TOKENS  524288

// ---------------- Scratch ----------------
__device__ float g_qkv[(size_t)TOKENS * 288];
__device__ float g_o  [(size_t)TOKENS * 96];
__device__ float g_x1 [(size_t)TOKENS * 96];

__device__ __forceinline__ int token_to_pixel(int tw) {
    int win = tw >> 6, p = tw & 63;
    int b  = win >> 10;
    int rem = win & 1023;
    int wh = rem >> 5, ww = rem & 31;
    int hh = (wh << 3) + (p >> 3);
    int wp = (ww << 3) + (p & 7);
    int sh = (hh + SHIFT) & 255;
    int sw = (wp + SHIFT) & 255;
    return (b << 16) | (sh << 8) | sw;
}

// ---------------- packed f32x2 helpers ----------------
__device__ __forceinline__ unsigned long long ffma2(
    unsigned long long a, unsigned long long b, unsigned long long c) {
    unsigned long long d;
    asm("fma.rn.f32x2 %0, %1, %2, %3;" : "=l"(d) : "l"(a), "l"(b), "l"(c));
    return d;
}
__device__ __forceinline__ unsigned long long pack_dup(float w) {
    unsigned long long p;
    unsigned int u = __float_as_uint(w);
    asm("mov.b64 %0, {%1, %1};" : "=l"(p) : "r"(u));
    return p;
}
__device__ __forceinline__ void unpack2(unsigned long long p, float& lo, float& hi) {
    unsigned int a, b;
    asm("mov.b64 {%0, %1}, %2;" : "=r"(a), "=r"(b) : "l"(p));
    lo = __uint_as_float(a);
    hi = __uint_as_float(b);
}
__device__ __forceinline__ float gelu_f(float v) {
    float inner = 0.7978845608028654f * (v + 0.044715f * v * v * v);
    return 0.5f * v * (1.0f + tanhf(inner));
}

// =======================================================================
// Kernel 1: LN1 + shifted-window gather + QKV GEMM (K=96, N=288)
// 32 tokens/block, 288 threads. GEMM: J=4 cols, T=8 tokens, f32x2.
// =======================================================================
__global__ __launch_bounds__(288) void qkv_kernel(
    const float* __restrict__ x, const float* __restrict__ lng,
    const float* __restrict__ lnb, const float* __restrict__ W,
    const float* __restrict__ bias)
{
    __shared__ float s_raw[32][100];
    __shared__ float s_lnT[96][36];      // transposed: [k][token]
    const int tid  = threadIdx.x;
    const int tok0 = blockIdx.x * 32;

    for (int l = tid; l < 32 * 24; l += 288) {
        int t = l / 24, k4 = l - t * 24;
        int gidx = token_to_pixel(tok0 + t);
        *(float4*)&s_raw[t][k4 * 4] = *(const float4*)&x[(size_t)gidx * 96 + k4 * 4];
    }
    __syncthreads();

    const int warp = tid >> 5, lane = tid & 31;
    for (int t = warp; t < 32; t += 9) {
        float v0 = s_raw[t][lane], v1 = s_raw[t][lane + 32], v2 = s_raw[t][lane + 64];
        float s = v0 + v1 + v2;
        float q = v0 * v0 + v1 * v1 + v2 * v2;
        #pragma unroll
        for (int o = 16; o; o >>= 1) {
            s += __shfl_xor_sync(0xffffffffu, s, o);
            q += __shfl_xor_sync(0xffffffffu, q, o);
        }
        float mu  = s * (1.0f / 96.0f);
        float var = q * (1.0f / 96.0f) - mu * mu;
        float rs  = rsqrtf(var + 1e-5f);
        s_lnT[lane][t]      = (v0 - mu) * rs * lng[lane]      + lnb[lane];
        s_lnT[lane + 32][t] = (v1 - mu) * rs * lng[lane + 32] + lnb[lane + 32];
        s_lnT[lane + 64][t] = (v2 - mu) * rs * lng[lane + 64] + lnb[lane + 64];
    }
    __syncthreads();

    const int jg = tid >> 2, tg = tid & 3;
    const int j0 = jg * 4, t0 = tg * 8;
    unsigned long long acc[4][4];
    #pragma unroll
    for (int jj = 0; jj < 4; ++jj) {
        unsigned long long b = pack_dup(bias[j0 + jj]);
        #pragma unroll
        for (int p = 0; p < 4; ++p) acc[p][jj] = b;
    }
    #pragma unroll 2
    for (int k = 0; k < 96; ++k) {
        float4 w4 = *(const float4*)&W[k * 288 + j0];
        unsigned long long w0 = pack_dup(w4.x), w1 = pack_dup(w4.y),
                           w2 = pack_dup(w4.z), w3 = pack_dup(w4.w);
        ulonglong2 a01 = *(const ulonglong2*)&s_lnT[k][t0];
        ulonglong2 a23 = *(const ulonglong2*)&s_lnT[k][t0 + 4];
        acc[0][0] = ffma2(a01.x, w0, acc[0][0]); acc[0][1] = ffma2(a01.x, w1, acc[0][1]);
        acc[0][2] = ffma2(a01.x, w2, acc[0][2]); acc[0][3] = ffma2(a01.x, w3, acc[0][3]);
        acc[1][0] = ffma2(a01.y, w0, acc[1][0]); acc[1][1] = ffma2(a01.y, w1, acc[1][1]);
        acc[1][2] = ffma2(a01.y, w2, acc[1][2]); acc[1][3] = ffma2(a01.y, w3, acc[1][3]);
        acc[2][0] = ffma2(a23.x, w0, acc[2][0]); acc[2][1] = ffma2(a23.x, w1, acc[2][1]);
        acc[2][2] = ffma2(a23.x, w2, acc[2][2]); acc[2][3] = ffma2(a23.x, w3, acc[2][3]);
        acc[3][0] = ffma2(a23.y, w0, acc[3][0]); acc[3][1] = ffma2(a23.y, w1, acc[3][1]);
        acc[3][2] = ffma2(a23.y, w2, acc[3][2]); acc[3][3] = ffma2(a23.y, w3, acc[3][3]);
    }
    #pragma unroll
    for (int p = 0; p < 4; ++p) {
        float lo[4], hi[4];
        #pragma unroll
        for (int jj = 0; jj < 4; ++jj) unpack2(acc[p][jj], lo[jj], hi[jj]);
        int t = t0 + 2 * p;
        *(float4*)&g_qkv[(size_t)(tok0 + t) * 288 + j0]     = make_float4(lo[0], lo[1], lo[2], lo[3]);
        *(float4*)&g_qkv[(size_t)(tok0 + t + 1) * 288 + j0] = make_float4(hi[0], hi[1], hi[2], hi[3]);
    }
}

// =======================================================================
// Kernel 2: windowed attention (unchanged from R2). grid (NWIN, HEADS), 128 thr.
// =======================================================================
__global__ __launch_bounds__(128) void attn_kernel(const float* __restrict__ rpbt)
{
    __shared__ float s_q[64][20], s_k[64][20], s_v[64][20];
    __shared__ float s_att[64][68];
    __shared__ int   s_reg[64];

    const int win = blockIdx.x;
    const int h   = blockIdx.y;
    const int tid = threadIdx.x;
    const int tokbase = win << 6;

    for (int l = tid; l < 3 * 64 * 4; l += 128) {
        int mat = l >> 8;
        int rem = l & 255;
        int row = rem >> 2, c4 = rem & 3;
        float4 v = *(const float4*)&g_qkv[(size_t)(tokbase + row) * 288 + mat * 96 + h * 16 + c4 * 4];
        if (mat == 0) {
            v.x *= 0.25f; v.y *= 0.25f; v.z *= 0.25f; v.w *= 0.25f;
            *(float4*)&s_q[row][c4 * 4] = v;
        } else if (mat == 1) *(float4*)&s_k[row][c4 * 4] = v;
        else                 *(float4*)&s_v[row][c4 * 4] = v;
    }
    if (tid < 64) {
        int rem = win & 1023;
        int wh = rem >> 5, ww = rem & 31;
        int hh = (wh << 3) + (tid >> 3);
        int wp = (ww << 3) + (tid & 7);
        int rh = (hh < 248) ? 0 : ((hh < 252) ? 1 : 2);
        int rw = (wp < 248) ? 0 : ((wp < 252) ? 1 : 2);
        s_reg[tid] = rh * 3 + rw;
    }
    __syncthreads();

    const int i    = tid >> 1;
    const int half = tid & 1;
    {
        float4 q0 = *(const float4*)&s_q[i][0];
        float4 q1 = *(const float4*)&s_q[i][4];
        float4 q2 = *(const float4*)&s_q[i][8];
        float4 q3 = *(const float4*)&s_q[i][12];
        const int regi = s_reg[i];
        const int ri = i >> 3, ci = i & 7;
        #pragma unroll 4
        for (int jo = 0; jo < 32; ++jo) {
            int jj = half * 32 + jo;
            float4 k0 = *(const float4*)&s_k[jj][0];
            float4 k1 = *(const float4*)&s_k[jj][4];
            float4 k2 = *(const float4*)&s_k[jj][8];
            float4 k3 = *(const float4*)&s_k[jj][12];
            float a = q0.x*k0.x + q0.y*k0.y + q0.z*k0.z + q0.w*k0.w
                    + q1.x*k1.x + q1.y*k1.y + q1.z*k1.z + q1.w*k1.w
                    + q2.x*k2.x + q2.y*k2.y + q2.z*k2.z + q2.w*k2.w
                    + q3.x*k3.x + q3.y*k3.y + q3.z*k3.z + q3.w*k3.w;
            int idx = ((ri - (jj >> 3) + 7) * 15 + (ci - (jj & 7) + 7));
            a += rpbt[idx * 6 + h];
            if (regi != s_reg[jj]) a -= 100.0f;
            s_att[i][jj] = a;
        }
    }
    __syncthreads();

    const int warp = tid >> 5, lane = tid & 31;
    for (int rr = 0; rr < 16; ++rr) {
        int r = warp + 4 * rr;
        float a0 = s_att[r][lane], a1 = s_att[r][lane + 32];
        float m = fmaxf(a0, a1);
        #pragma unroll
        for (int o = 16; o; o >>= 1) m = fmaxf(m, __shfl_xor_sync(0xffffffffu, m, o));
        float e0 = __expf(a0 - m), e1 = __expf(a1 - m);
        float s = e0 + e1;
        #pragma unroll
        for (int o = 16; o; o >>= 1) s += __shfl_xor_sync(0xffffffffu, s, o);
        float inv = 1.0f / s;
        s_att[r][lane]      = e0 * inv;
        s_att[r][lane + 32] = e1 * inv;
    }
    __syncthreads();

    {
        const int d0 = half * 8;
        float acc[8];
        #pragma unroll
        for (int d = 0; d < 8; ++d) acc[d] = 0.0f;
        for (int jj = 0; jj < 64; jj += 4) {
            float4 at = *(const float4*)&s_att[i][jj];
            #pragma unroll
            for (int u = 0; u < 4; ++u) {
                float a = (u == 0) ? at.x : (u == 1) ? at.y : (u == 2) ? at.z : at.w;
                float4 v0 = *(const float4*)&s_v[jj + u][d0];
                float4 v1 = *(const float4*)&s_v[jj + u][d0 + 4];
                acc[0] += a * v0.x; acc[1] += a * v0.y;
                acc[2] += a * v0.z; acc[3] += a * v0.w;
                acc[4] += a * v1.x; acc[5] += a * v1.y;
                acc[6] += a * v1.z; acc[7] += a * v1.w;
            }
        }
        float* dst = &g_o[(size_t)(tokbase + i) * 96 + h * 16 + d0];
        *(float4*)&dst[0] = make_float4(acc[0], acc[1], acc[2], acc[3]);
        *(float4*)&dst[4] = make_float4(acc[4], acc[5], acc[6], acc[7]);
    }
}

// =======================================================================
// Kernel 3: proj GEMM + window-reverse/unshift scatter + residual
// 64 tokens/block, 192 threads. J=4, T=8, f32x2.
// =======================================================================
__global__ __launch_bounds__(192) void proj_kernel(
    const float* __restrict__ W, const float* __restrict__ bias,
    const float* __restrict__ x)
{
    __shared__ float s_oT[96][68];   // transposed [k][token]
    const int tid  = threadIdx.x;
    const int tok0 = blockIdx.x * 64;

    for (int l = tid; l < 64 * 24; l += 192) {
        int t = l / 24, k4 = l - t * 24;
        float4 v = *(const float4*)&g_o[(size_t)(tok0 + t) * 96 + k4 * 4];
        s_oT[k4 * 4 + 0][t] = v.x;
        s_oT[k4 * 4 + 1][t] = v.y;
        s_oT[k4 * 4 + 2][t] = v.z;
        s_oT[k4 * 4 + 3][t] = v.w;
    }
    __syncthreads();

    const int jg = tid >> 3, tg = tid & 7;
    const int j0 = jg * 4, t0 = tg * 8;
    unsigned long long acc[4][4];
    #pragma unroll
    for (int jj = 0; jj < 4; ++jj) {
        unsigned long long b = pack_dup(bias[j0 + jj]);
        #pragma unroll
        for (int p = 0; p < 4; ++p) acc[p][jj] = b;
    }
    #pragma unroll 2
    for (int k = 0; k < 96; ++k) {
        float4 w4 = *(const float4*)&W[k * 96 + j0];
        unsigned long long w0 = pack_dup(w4.x), w1 = pack_dup(w4.y),
                           w2 = pack_dup(w4.z), w3 = pack_dup(w4.w);
        ulonglong2 a01 = *(const ulonglong2*)&s_oT[k][t0];
        ulonglong2 a23 = *(const ulonglong2*)&s_oT[k][t0 + 4];
        acc[0][0] = ffma2(a01.x, w0, acc[0][0]); acc[0][1] = ffma2(a01.x, w1, acc[0][1]);
        acc[0][2] = ffma2(a01.x, w2, acc[0][2]); acc[0][3] = ffma2(a01.x, w3, acc[0][3]);
        acc[1][0] = ffma2(a01.y, w0, acc[1][0]); acc[1][1] = ffma2(a01.y, w1, acc[1][1]);
        acc[1][2] = ffma2(a01.y, w2, acc[1][2]); acc[1][3] = ffma2(a01.y, w3, acc[1][3]);
        acc[2][0] = ffma2(a23.x, w0, acc[2][0]); acc[2][1] = ffma2(a23.x, w1, acc[2][1]);
        acc[2][2] = ffma2(a23.x, w2, acc[2][2]); acc[2][3] = ffma2(a23.x, w3, acc[2][3]);
        acc[3][0] = ffma2(a23.y, w0, acc[3][0]); acc[3][1] = ffma2(a23.y, w1, acc[3][1]);
        acc[3][2] = ffma2(a23.y, w2, acc[3][2]); acc[3][3] = ffma2(a23.y, w3, acc[3][3]);
    }
    #pragma unroll
    for (int p = 0; p < 4; ++p) {
        float lo[4], hi[4];
        #pragma unroll
        for (int jj = 0; jj < 4; ++jj) unpack2(acc[p][jj], lo[jj], hi[jj]);
        int t = t0 + 2 * p;
        {
            size_t gi = (size_t)token_to_pixel(tok0 + t) * 96 + j0;
            float4 xr = *(const float4*)&x[gi];
            *(float4*)&g_x1[gi] = make_float4(xr.x + lo[0], xr.y + lo[1],
                                              xr.z + lo[2], xr.w + lo[3]);
        }
        {
            size_t gi = (size_t)token_to_pixel(tok0 + t + 1) * 96 + j0;
            float4 xr = *(const float4*)&x[gi];
            *(float4*)&g_x1[gi] = make_float4(xr.x + hi[0], xr.y + hi[1],
                                              xr.z + hi[2], xr.w + hi[3]);
        }
    }
}

// =======================================================================
// Kernel 4: LN2 + MLP1 + gelu + MLP2 + residual.
// 32 tokens/block, 384 threads, dynamic smem 94720 B.
// =======================================================================
#define MLP_SMEM_BYTES 94720
__global__ __launch_bounds__(384) void mlp_kernel(
    const float* __restrict__ lng, const float* __restrict__ lnb,
    const float* __restrict__ W1, const float* __restrict__ b1,
    const float* __restrict__ W2, const float* __restrict__ b2,
    float* __restrict__ out)
{
    extern __shared__ float smem[];
    float (*s_raw)[100]  = (float(*)[100])(smem);                    // 32 x 100
    float (*s_lnT)[36]   = (float(*)[36])(smem + 3200);              // 96 x 36
    float (*s_hidT)[36]  = (float(*)[36])(smem + 3200 + 3456);       // 384 x 36
    float (*s_part)[100] = (float(*)[100])(smem + 3200 + 3456 + 13824); // 32 x 100

    const int tid  = threadIdx.x;
    const int tok0 = blockIdx.x * 32;

    for (int l = tid; l < 32 * 24; l += 384) {
        int t = l / 24, k4 = l - t * 24;
        *(float4*)&s_raw[t][k4 * 4] = *(const float4*)&g_x1[(size_t)(tok0 + t) * 96 + k4 * 4];
    }
    __syncthreads();

    const int warp = tid >> 5, lane = tid & 31;
    for (int t = warp; t < 32; t += 12) {
        float v0 = s_raw[t][lane], v1 = s_raw[t][lane + 32], v2 = s_raw[t][lane + 64];
        float s = v0 + v1 + v2;
        float q = v0 * v0 + v1 * v1 + v2 * v2;
        #pragma unroll
        for (int o = 16; o; o >>= 1) {
            s += __shfl_xor_sync(0xffffffffu, s, o);
            q += __shfl_xor_sync(0xffffffffu, q, o);
        }
        float mu  = s * (1.0f / 96.0f);
        float var = q * (1.0f / 96.0f) - mu * mu;
        float rs  = rsqrtf(var + 1e-5f);
        s_lnT[lane][t]      = (v0 - mu) * rs * lng[lane]      + lnb[lane];
        s_lnT[lane + 32][t] = (v1 - mu) * rs * lng[lane + 32] + lnb[lane + 32];
        s_lnT[lane + 64][t] = (v2 - mu) * rs * lng[lane + 64] + lnb[lane + 64];
    }
    __syncthreads();

    // ---- MLP1 + gelu -> s_hidT (transposed) ----
    {
        const int jg = tid >> 2, tg = tid & 3;   // 96 x 4
        const int j0 = jg * 4, t0 = tg * 8;
        unsigned long long acc[4][4];
        #pragma unroll
        for (int jj = 0; jj < 4; ++jj) {
            unsigned long long b = pack_dup(b1[j0 + jj]);
            #pragma unroll
            for (int p = 0; p < 4; ++p) acc[p][jj] = b;
        }
        #pragma unroll 2
        for (int k = 0; k < 96; ++k) {
            float4 w4 = *(const float4*)&W1[k * 384 + j0];
            unsigned long long w0 = pack_dup(w4.x), w1 = pack_dup(w4.y),
                               w2 = pack_dup(w4.z), w3 = pack_dup(w4.w);
            ulonglong2 a01 = *(const ulonglong2*)&s_lnT[k][t0];
            ulonglong2 a23 = *(const ulonglong2*)&s_lnT[k][t0 + 4];
            acc[0][0] = ffma2(a01.x, w0, acc[0][0]); acc[0][1] = ffma2(a01.x, w1, acc[0][1]);
            acc[0][2] = ffma2(a01.x, w2, acc[0][2]); acc[0][3] = ffma2(a01.x, w3, acc[0][3]);
            acc[1][0] = ffma2(a01.y, w0, acc[1][0]); acc[1][1] = ffma2(a01.y, w1, acc[1][1]);
            acc[1][2] = ffma2(a01.y, w2, acc[1][2]); acc[1][3] = ffma2(a01.y, w3, acc[1][3]);
            acc[2][0] = ffma2(a23.x, w0, acc[2][0]); acc[2][1] = ffma2(a23.x, w1, acc[2][1]);
            acc[2][2] = ffma2(a23.x, w2, acc[2][2]); acc[2][3] = ffma2(a23.x, w3, acc[2][3]);
            acc[3][0] = ffma2(a23.y, w0, acc[3][0]); acc[3][1] = ffma2(a23.y, w1, acc[3][1]);
            acc[3][2] = ffma2(a23.y, w2, acc[3][2]); acc[3][3] = ffma2(a23.y, w3, acc[3][3]);
        }
        float v[4][8];
        #pragma unroll
        for (int p = 0; p < 4; ++p) {
            #pragma unroll
            for (int jj = 0; jj < 4; ++jj) {
                float lo, hi;
                unpack2(acc[p][jj], lo, hi);
                v[jj][2 * p]     = gelu_f(lo);
                v[jj][2 * p + 1] = gelu_f(hi);
            }
        }
        #pragma unroll
        for (int jj = 0; jj < 4; ++jj) {
            *(float4*)&s_hidT[j0 + jj][t0]     = make_float4(v[jj][0], v[jj][1], v[jj][2], v[jj][3]);
            *(float4*)&s_hidT[j0 + jj][t0 + 4] = make_float4(v[jj][4], v[jj][5], v[jj][6], v[jj][7]);
        }
    }
    __syncthreads();

    // ---- MLP2 (K=384, 2-way K split) + residual ----
    unsigned long long acc2[4][4];
    int j0 = 0, t0 = 0, ks = 0;
    if (tid < 192) {
        ks = tid / 96;
        int r = tid % 96;
        int jg = r >> 2, tg = r & 3;
        j0 = jg * 4; t0 = tg * 8;
        #pragma unroll
        for (int jj = 0; jj < 4; ++jj) {
            unsigned long long b = (ks == 0) ? pack_dup(b2[j0 + jj]) : 0ull;
            #pragma unroll
            for (int p = 0; p < 4; ++p) acc2[p][jj] = b;
        }
        const int kbeg = ks * 192, kend = kbeg + 192;
        #pragma unroll 2
        for (int k = kbeg; k < kend; ++k) {
            float4 w4 = *(const float4*)&W2[k * 96 + j0];
            unsigned long long w0 = pack_dup(w4.x), w1 = pack_dup(w4.y),
                               w2 = pack_dup(w4.z), w3 = pack_dup(w4.w);
            ulonglong2 a01 = *(const ulonglong2*)&s_hidT[k][t0];
            ulonglong2 a23 = *(const ulonglong2*)&s_hidT[k][t0 + 4];
            acc2[0][0] = ffma2(a01.x, w0, acc2[0][0]); acc2[0][1] = ffma2(a01.x, w1, acc2[0][1]);
            acc2[0][2] = ffma2(a01.x, w2, acc2[0][2]); acc2[0][3] = ffma2(a01.x, w3, acc2[0][3]);
            acc2[1][0] = ffma2(a01.y, w0, acc2[1][0]); acc2[1][1] = ffma2(a01.y, w1, acc2[1][1]);
            acc2[1][2] = ffma2(a01.y, w2, acc2[1][2]); acc2[1][3] = ffma2(a01.y, w3, acc2[1][3]);
            acc2[2][0] = ffma2(a23.x, w0, acc2[2][0]); acc2[2][1] = ffma2(a23.x, w1, acc2[2][1]);
            acc2[2][2] = ffma2(a23.x, w2, acc2[2][2]); acc2[2][3] = ffma2(a23.x, w3, acc2[2][3]);
            acc2[3][0] = ffma2(a23.y, w0, acc2[3][0]); acc2[3][1] = ffma2(a23.y, w1, acc2[3][1]);
            acc2[3][2] = ffma2(a23.y, w2, acc2[3][2]); acc2[3][3] = ffma2(a23.y, w3, acc2[3][3]);
        }
        if (ks == 0) {
            #pragma unroll
            for (int p = 0; p < 4; ++p) {
                float lo[4], hi[4];
                #pragma unroll
                for (int jj = 0; jj < 4; ++jj) unpack2(acc2[p][jj], lo[jj], hi[jj]);
                int t = t0 + 2 * p;
                *(float4*)&s_part[t][j0]     = make_float4(lo[0], lo[1], lo[2], lo[3]);
                *(float4*)&s_part[t + 1][j0] = make_float4(hi[0], hi[1], hi[2], hi[3]);
            }
        }
    }
    __syncthreads();
    if (tid < 192 && ks == 1) {
        #pragma unroll
        for (int p = 0; p < 4; ++p) {
            float lo[4], hi[4];
            #pragma unroll
            for (int jj = 0; jj < 4; ++jj) unpack2(acc2[p][jj], lo[jj], hi[jj]);
            int t = t0 + 2 * p;
            {
                float4 pa = *(const float4*)&s_part[t][j0];
                float4 rr = *(const float4*)&s_raw[t][j0];
                *(float4*)&out[(size_t)(tok0 + t) * 96 + j0] =
                    make_float4(rr.x + pa.x + lo[0], rr.y + pa.y + lo[1],
                                rr.z + pa.z + lo[2], rr.w + pa.w + lo[3]);
            }
            {
                float4 pa = *(const float4*)&s_part[t + 1][j0];
                float4 rr = *(const float4*)&s_raw[t + 1][j0];
                *(float4*)&out[(size_t)(tok0 + t + 1) * 96 + j0] =
                    make_float4(rr.x + pa.x + hi[0], rr.y + pa.y + hi[1],
                                rr.z + pa.z + hi[2], rr.w + pa.w + hi[3]);
            }
        }
    }
}

// =======================================================================
extern "C" void kernel_launch(void* const* d_in, const int* in_sizes, int n_in,
                              void* d_out, int out_size)
{
    const float* x         = (const float*)d_in[0];
    const float* ln1_scale = (const float*)d_in[1];
    const float* ln1_bias  = (const float*)d_in[2];
    const float* qkv_w     = (const float*)d_in[3];
    const float* qkv_b     = (const float*)d_in[4];
    const float* rpbt      = (const float*)d_in[5];
    const float* proj_w    = (const float*)d_in[6];
    const float* proj_b    = (const float*)d_in[7];
    const float* ln2_scale = (const float*)d_in[8];
    const float* ln2_bias  = (const float*)d_in[9];
    const float* mlp_w1    = (const float*)d_in[10];
    const float* mlp_b1    = (const float*)d_in[11];
    const float* mlp_w2    = (const float*)d_in[12];
    const float* mlp_b2    = (const float*)d_in[13];
    float* out = (float*)d_out;

    cudaFuncSetAttribute(mlp_kernel, cudaFuncAttributeMaxDynamicSharedMemorySize,
                         MLP_SMEM_BYTES);

    qkv_kernel<<<TOKENS / 32, 288>>>(x, ln1_scale, ln1_bias, qkv_w, qkv_b);
    attn_kernel<<<dim3(NWIN, HEADS), 128>>>(rpbt);
    proj_kernel<<<TOKENS / 64, 192>>>(proj_w, proj_b, x);
    mlp_kernel<<<TOKENS / 32, 384, MLP_SMEM_BYTES>>>(ln2_scale, ln2_bias,
                                                     mlp_w1, mlp_b1,
                                                     mlp_w2, mlp_b2, out);
}

// round 4
// speedup vs baseline: 1.7383x; 1.1984x over previous
#include <cuda_runtime.h>
#include <cuda_bf16.h>
#include <mma.h>
#include <cstdint>

using namespace nvcuda;

// ---------------- Problem constants ----------------
#define BATCH   8
#define HRES    256
#define WRES    256
#define CDIM    96
#define HEADS   6
#define WS      8
#define SHIFT   4
#define NWIN    8192
#define TOKENS  524288

// ---------------- Scratch ----------------
__device__ float g_qkv[(size_t)TOKENS * 288];
__device__ float g_o  [(size_t)TOKENS * 96];
__device__ float g_x1 [(size_t)TOKENS * 96];

// bf16 weight copies (converted once per launch)
__device__ __align__(128) __nv_bfloat16 g_qkvw_bf[96 * 288];
__device__ __align__(128) __nv_bfloat16 g_projw_bf[96 * 96];
__device__ __align__(128) __nv_bfloat16 g_w1_bf[96 * 384];
__device__ __align__(128) __nv_bfloat16 g_w2_bf[384 * 96];

__device__ __forceinline__ int token_to_pixel(int tw) {
    int win = tw >> 6, p = tw & 63;
    int b  = win >> 10;
    int rem = win & 1023;
    int wh = rem >> 5, ww = rem & 31;
    int hh = (wh << 3) + (p >> 3);
    int wp = (ww << 3) + (p & 7);
    int sh = (hh + SHIFT) & 255;
    int sw = (wp + SHIFT) & 255;
    return (b << 16) | (sh << 8) | sw;
}

__device__ __forceinline__ float gelu_f(float v) {
    float inner = 0.7978845608028654f * (v + 0.044715f * v * v * v);
    return 0.5f * v * (1.0f + tanhf(inner));
}

typedef wmma::fragment<wmma::matrix_a, 16, 16, 16, __nv_bfloat16, wmma::row_major> FragA;
typedef wmma::fragment<wmma::matrix_b, 16, 16, 16, __nv_bfloat16, wmma::row_major> FragB;
typedef wmma::fragment<wmma::accumulator, 16, 16, 16, float> FragC;

// =======================================================================
// Kernel 0: convert weights fp32 -> bf16 (once per launch)
// =======================================================================
__global__ void conv_weights(const float* __restrict__ qkvw,
                             const float* __restrict__ projw,
                             const float* __restrict__ w1,
                             const float* __restrict__ w2)
{
    int i = blockIdx.x * 256 + threadIdx.x;
    if (i < 96 * 288) g_qkvw_bf[i] = __float2bfloat16(qkvw[i]);
    if (i < 96 * 96)  g_projw_bf[i] = __float2bfloat16(projw[i]);
    if (i < 96 * 384) g_w1_bf[i]   = __float2bfloat16(w1[i]);
    if (i < 384 * 96) g_w2_bf[i]   = __float2bfloat16(w2[i]);
}

// =======================================================================
// Kernel 1: LN1 + shifted-window gather + QKV GEMM (bf16 HMMA)
// 64 tokens/block, 256 threads (8 warps = 4M x 2N)
// =======================================================================
__global__ __launch_bounds__(256) void qkv_kernel(
    const float* __restrict__ x, const float* __restrict__ lng,
    const float* __restrict__ lnb, const float* __restrict__ bias)
{
    __shared__ float s_raw[64][96];
    __shared__ alignas(32) __nv_bfloat16 s_a[64][104];
    __shared__ alignas(32) float s_wb[8][16][20];

    const int tid  = threadIdx.x;
    const int tok0 = blockIdx.x * 64;
    const int warp = tid >> 5, lane = tid & 31;

    for (int l = tid; l < 64 * 24; l += 256) {
        int t = l / 24, k4 = l - t * 24;
        int gidx = token_to_pixel(tok0 + t);
        *(float4*)&s_raw[t][k4 * 4] = *(const float4*)&x[(size_t)gidx * 96 + k4 * 4];
    }
    __syncthreads();

    for (int t = warp; t < 64; t += 8) {
        float v0 = s_raw[t][lane], v1 = s_raw[t][lane + 32], v2 = s_raw[t][lane + 64];
        float s = v0 + v1 + v2;
        float q = v0 * v0 + v1 * v1 + v2 * v2;
        #pragma unroll
        for (int o = 16; o; o >>= 1) {
            s += __shfl_xor_sync(0xffffffffu, s, o);
            q += __shfl_xor_sync(0xffffffffu, q, o);
        }
        float mu  = s * (1.0f / 96.0f);
        float var = q * (1.0f / 96.0f) - mu * mu;
        float rs  = rsqrtf(var + 1e-5f);
        s_a[t][lane]      = __float2bfloat16((v0 - mu) * rs * lng[lane]      + lnb[lane]);
        s_a[t][lane + 32] = __float2bfloat16((v1 - mu) * rs * lng[lane + 32] + lnb[lane + 32]);
        s_a[t][lane + 64] = __float2bfloat16((v2 - mu) * rs * lng[lane + 64] + lnb[lane + 64]);
    }
    __syncthreads();

    const int mt = warp & 3, wn = warp >> 2;
    const int m0 = mt * 16;
    const int r  = lane >> 1, c0 = (lane & 1) * 8;

    for (int chunk = 0; chunk < 3; ++chunk) {
        int ntb = wn * 9 + chunk * 3;
        FragC acc[3];
        #pragma unroll
        for (int c = 0; c < 3; ++c) wmma::fill_fragment(acc[c], 0.0f);
        #pragma unroll
        for (int k = 0; k < 6; ++k) {
            FragA a;
            wmma::load_matrix_sync(a, &s_a[m0][k * 16], 104);
            #pragma unroll
            for (int c = 0; c < 3; ++c) {
                FragB b;
                wmma::load_matrix_sync(b, &g_qkvw_bf[(k * 16) * 288 + (ntb + c) * 16], 288);
                wmma::mma_sync(acc[c], a, b, acc[c]);
            }
        }
        #pragma unroll
        for (int c = 0; c < 3; ++c) {
            int n0 = (ntb + c) * 16;
            wmma::store_matrix_sync(&s_wb[warp][0][0], acc[c], 20, wmma::mem_row_major);
            __syncwarp();
            float* row = s_wb[warp][r];
            #pragma unroll
            for (int i = 0; i < 8; ++i) {
                float v = row[c0 + i] + bias[n0 + c0 + i];
                g_qkv[(size_t)(tok0 + m0 + r) * 288 + n0 + c0 + i] = v;
            }
            __syncwarp();
        }
    }
}

// =======================================================================
// Kernel 2: windowed attention (unchanged). grid (NWIN, HEADS), 128 thr.
// =======================================================================
__global__ __launch_bounds__(128) void attn_kernel(const float* __restrict__ rpbt)
{
    __shared__ float s_q[64][20], s_k[64][20], s_v[64][20];
    __shared__ float s_att[64][68];
    __shared__ int   s_reg[64];

    const int win = blockIdx.x;
    const int h   = blockIdx.y;
    const int tid = threadIdx.x;
    const int tokbase = win << 6;

    for (int l = tid; l < 3 * 64 * 4; l += 128) {
        int mat = l >> 8;
        int rem = l & 255;
        int row = rem >> 2, c4 = rem & 3;
        float4 v = *(const float4*)&g_qkv[(size_t)(tokbase + row) * 288 + mat * 96 + h * 16 + c4 * 4];
        if (mat == 0) {
            v.x *= 0.25f; v.y *= 0.25f; v.z *= 0.25f; v.w *= 0.25f;
            *(float4*)&s_q[row][c4 * 4] = v;
        } else if (mat == 1) *(float4*)&s_k[row][c4 * 4] = v;
        else                 *(float4*)&s_v[row][c4 * 4] = v;
    }
    if (tid < 64) {
        int rem = win & 1023;
        int wh = rem >> 5, ww = rem & 31;
        int hh = (wh << 3) + (tid >> 3);
        int wp = (ww << 3) + (tid & 7);
        int rh = (hh < 248) ? 0 : ((hh < 252) ? 1 : 2);
        int rw = (wp < 248) ? 0 : ((wp < 252) ? 1 : 2);
        s_reg[tid] = rh * 3 + rw;
    }
    __syncthreads();

    const int i    = tid >> 1;
    const int half = tid & 1;
    {
        float4 q0 = *(const float4*)&s_q[i][0];
        float4 q1 = *(const float4*)&s_q[i][4];
        float4 q2 = *(const float4*)&s_q[i][8];
        float4 q3 = *(const float4*)&s_q[i][12];
        const int regi = s_reg[i];
        const int ri = i >> 3, ci = i & 7;
        #pragma unroll 4
        for (int jo = 0; jo < 32; ++jo) {
            int jj = half * 32 + jo;
            float4 k0 = *(const float4*)&s_k[jj][0];
            float4 k1 = *(const float4*)&s_k[jj][4];
            float4 k2 = *(const float4*)&s_k[jj][8];
            float4 k3 = *(const float4*)&s_k[jj][12];
            float a = q0.x*k0.x + q0.y*k0.y + q0.z*k0.z + q0.w*k0.w
                    + q1.x*k1.x + q1.y*k1.y + q1.z*k1.z + q1.w*k1.w
                    + q2.x*k2.x + q2.y*k2.y + q2.z*k2.z + q2.w*k2.w
                    + q3.x*k3.x + q3.y*k3.y + q3.z*k3.z + q3.w*k3.w;
            int idx = ((ri - (jj >> 3) + 7) * 15 + (ci - (jj & 7) + 7));
            a += rpbt[idx * 6 + h];
            if (regi != s_reg[jj]) a -= 100.0f;
            s_att[i][jj] = a;
        }
    }
    __syncthreads();

    const int warp = tid >> 5, lane = tid & 31;
    for (int rr = 0; rr < 16; ++rr) {
        int r = warp + 4 * rr;
        float a0 = s_att[r][lane], a1 = s_att[r][lane + 32];
        float m = fmaxf(a0, a1);
        #pragma unroll
        for (int o = 16; o; o >>= 1) m = fmaxf(m, __shfl_xor_sync(0xffffffffu, m, o));
        float e0 = __expf(a0 - m), e1 = __expf(a1 - m);
        float s = e0 + e1;
        #pragma unroll
        for (int o = 16; o; o >>= 1) s += __shfl_xor_sync(0xffffffffu, s, o);
        float inv = 1.0f / s;
        s_att[r][lane]      = e0 * inv;
        s_att[r][lane + 32] = e1 * inv;
    }
    __syncthreads();

    {
        const int d0 = half * 8;
        float acc[8];
        #pragma unroll
        for (int d = 0; d < 8; ++d) acc[d] = 0.0f;
        for (int jj = 0; jj < 64; jj += 4) {
            float4 at = *(const float4*)&s_att[i][jj];
            #pragma unroll
            for (int u = 0; u < 4; ++u) {
                float a = (u == 0) ? at.x : (u == 1) ? at.y : (u == 2) ? at.z : at.w;
                float4 v0 = *(const float4*)&s_v[jj + u][d0];
                float4 v1 = *(const float4*)&s_v[jj + u][d0 + 4];
                acc[0] += a * v0.x; acc[1] += a * v0.y;
                acc[2] += a * v0.z; acc[3] += a * v0.w;
                acc[4] += a * v1.x; acc[5] += a * v1.y;
                acc[6] += a * v1.z; acc[7] += a * v1.w;
            }
        }
        float* dst = &g_o[(size_t)(tokbase + i) * 96 + h * 16 + d0];
        *(float4*)&dst[0] = make_float4(acc[0], acc[1], acc[2], acc[3]);
        *(float4*)&dst[4] = make_float4(acc[4], acc[5], acc[6], acc[7]);
    }
}

// =======================================================================
// Kernel 3: proj GEMM (bf16 HMMA) + unshift scatter + residual
// 64 tokens/block, 256 threads
// =======================================================================
__global__ __launch_bounds__(256) void proj_kernel(
    const float* __restrict__ bias, const float* __restrict__ x)
{
    __shared__ alignas(32) __nv_bfloat16 s_a[64][104];
    __shared__ alignas(32) float s_wb[8][16][20];

    const int tid  = threadIdx.x;
    const int tok0 = blockIdx.x * 64;
    const int warp = tid >> 5, lane = tid & 31;

    for (int l = tid; l < 64 * 24; l += 256) {
        int t = l / 24, k4 = l - t * 24;
        float4 v = *(const float4*)&g_o[(size_t)(tok0 + t) * 96 + k4 * 4];
        s_a[t][k4 * 4 + 0] = __float2bfloat16(v.x);
        s_a[t][k4 * 4 + 1] = __float2bfloat16(v.y);
        s_a[t][k4 * 4 + 2] = __float2bfloat16(v.z);
        s_a[t][k4 * 4 + 3] = __float2bfloat16(v.w);
    }
    __syncthreads();

    const int mt = warp & 3, wn = warp >> 2;
    const int m0 = mt * 16;
    const int r  = lane >> 1, c0 = (lane & 1) * 8;

    FragC acc[3];
    #pragma unroll
    for (int c = 0; c < 3; ++c) wmma::fill_fragment(acc[c], 0.0f);
    #pragma unroll
    for (int k = 0; k < 6; ++k) {
        FragA a;
        wmma::load_matrix_sync(a, &s_a[m0][k * 16], 104);
        #pragma unroll
        for (int c = 0; c < 3; ++c) {
            FragB b;
            wmma::load_matrix_sync(b, &g_projw_bf[(k * 16) * 96 + (wn * 3 + c) * 16], 96);
            wmma::mma_sync(acc[c], a, b, acc[c]);
        }
    }
    #pragma unroll
    for (int c = 0; c < 3; ++c) {
        int n0 = (wn * 3 + c) * 16;
        wmma::store_matrix_sync(&s_wb[warp][0][0], acc[c], 20, wmma::mem_row_major);
        __syncwarp();
        float* row = s_wb[warp][r];
        size_t gi = (size_t)token_to_pixel(tok0 + m0 + r) * 96;
        #pragma unroll
        for (int i = 0; i < 8; ++i) {
            float v = row[c0 + i] + bias[n0 + c0 + i];
            g_x1[gi + n0 + c0 + i] = x[gi + n0 + c0 + i] + v;
        }
        __syncwarp();
    }
}

// =======================================================================
// Kernel 4: LN2 + MLP1 + gelu + MLP2 + residual (bf16 HMMA)
// 64 tokens/block, 256 threads, 96 KB dynamic smem
// =======================================================================
#define MLP_SMEM_BYTES 98304
__global__ __launch_bounds__(256) void mlp_kernel(
    const float* __restrict__ lng, const float* __restrict__ lnb,
    const float* __restrict__ b1, const float* __restrict__ b2,
    float* __restrict__ out)
{
    extern __shared__ char smem[];
    float         (*s_raw)[96] = (float(*)[96])(smem);                 // 24576 B
    __nv_bfloat16 (*s_a)[104]  = (__nv_bfloat16(*)[104])(smem + 24576); // 13312 B
    __nv_bfloat16 (*s_h)[392]  = (__nv_bfloat16(*)[392])(smem + 37888); // 50176 B
    float         (*s_wb)[16][20] = (float(*)[16][20])(smem + 88064);   // 10240 B

    const int tid  = threadIdx.x;
    const int tok0 = blockIdx.x * 64;
    const int warp = tid >> 5, lane = tid & 31;

    for (int l = tid; l < 64 * 24; l += 256) {
        int t = l / 24, k4 = l - t * 24;
        *(float4*)&s_raw[t][k4 * 4] = *(const float4*)&g_x1[(size_t)(tok0 + t) * 96 + k4 * 4];
    }
    __syncthreads();

    for (int t = warp; t < 64; t += 8) {
        float v0 = s_raw[t][lane], v1 = s_raw[t][lane + 32], v2 = s_raw[t][lane + 64];
        float s = v0 + v1 + v2;
        float q = v0 * v0 + v1 * v1 + v2 * v2;
        #pragma unroll
        for (int o = 16; o; o >>= 1) {
            s += __shfl_xor_sync(0xffffffffu, s, o);
            q += __shfl_xor_sync(0xffffffffu, q, o);
        }
        float mu  = s * (1.0f / 96.0f);
        float var = q * (1.0f / 96.0f) - mu * mu;
        float rs  = rsqrtf(var + 1e-5f);
        s_a[t][lane]      = __float2bfloat16((v0 - mu) * rs * lng[lane]      + lnb[lane]);
        s_a[t][lane + 32] = __float2bfloat16((v1 - mu) * rs * lng[lane + 32] + lnb[lane + 32]);
        s_a[t][lane + 64] = __float2bfloat16((v2 - mu) * rs * lng[lane + 64] + lnb[lane + 64]);
    }
    __syncthreads();

    const int mt = warp & 3, wn = warp >> 2;
    const int m0 = mt * 16;
    const int r  = lane >> 1, c0 = (lane & 1) * 8;

    // ---- MLP1 + gelu -> s_h bf16 ----
    for (int chunk = 0; chunk < 4; ++chunk) {
        int ntb = wn * 12 + chunk * 3;
        FragC acc[3];
        #pragma unroll
        for (int c = 0; c < 3; ++c) wmma::fill_fragment(acc[c], 0.0f);
        #pragma unroll
        for (int k = 0; k < 6; ++k) {
            FragA a;
            wmma::load_matrix_sync(a, &s_a[m0][k * 16], 104);
            #pragma unroll
            for (int c = 0; c < 3; ++c) {
                FragB b;
                wmma::load_matrix_sync(b, &g_w1_bf[(k * 16) * 384 + (ntb + c) * 16], 384);
                wmma::mma_sync(acc[c], a, b, acc[c]);
            }
        }
        #pragma unroll
        for (int c = 0; c < 3; ++c) {
            int n0 = (ntb + c) * 16;
            wmma::store_matrix_sync(&s_wb[warp][0][0], acc[c], 20, wmma::mem_row_major);
            __syncwarp();
            float* row = s_wb[warp][r];
            #pragma unroll
            for (int i = 0; i < 8; ++i) {
                float v = gelu_f(row[c0 + i] + b1[n0 + c0 + i]);
                s_h[m0 + r][n0 + c0 + i] = __float2bfloat16(v);
            }
            __syncwarp();
        }
    }
    __syncthreads();

    // ---- MLP2 + residual ----
    {
        FragC acc[3];
        #pragma unroll
        for (int c = 0; c < 3; ++c) wmma::fill_fragment(acc[c], 0.0f);
        for (int k = 0; k < 24; ++k) {
            FragA a;
            wmma::load_matrix_sync(a, &s_h[m0][k * 16], 392);
            #pragma unroll
            for (int c = 0; c < 3; ++c) {
                FragB b;
                wmma::load_matrix_sync(b, &g_w2_bf[(k * 16) * 96 + (wn * 3 + c) * 16], 96);
                wmma::mma_sync(acc[c], a, b, acc[c]);
            }
        }
        #pragma unroll
        for (int c = 0; c < 3; ++c) {
            int n0 = (wn * 3 + c) * 16;
            wmma::store_matrix_sync(&s_wb[warp][0][0], acc[c], 20, wmma::mem_row_major);
            __syncwarp();
            float* row = s_wb[warp][r];
            #pragma unroll
            for (int i = 0; i < 8; ++i) {
                float v = row[c0 + i] + b2[n0 + c0 + i];
                out[(size_t)(tok0 + m0 + r) * 96 + n0 + c0 + i] =
                    s_raw[m0 + r][n0 + c0 + i] + v;
            }
            __syncwarp();
        }
    }
}

// =======================================================================
extern "C" void kernel_launch(void* const* d_in, const int* in_sizes, int n_in,
                              void* d_out, int out_size)
{
    const float* x         = (const float*)d_in[0];
    const float* ln1_scale = (const float*)d_in[1];
    const float* ln1_bias  = (const float*)d_in[2];
    const float* qkv_w     = (const float*)d_in[3];
    const float* qkv_b     = (const float*)d_in[4];
    const float* rpbt      = (const float*)d_in[5];
    const float* proj_w    = (const float*)d_in[6];
    const float* proj_b    = (const float*)d_in[7];
    const float* ln2_scale = (const float*)d_in[8];
    const float* ln2_bias  = (const float*)d_in[9];
    const float* mlp_w1    = (const float*)d_in[10];
    const float* mlp_b1    = (const float*)d_in[11];
    const float* mlp_w2    = (const float*)d_in[12];
    const float* mlp_b2    = (const float*)d_in[13];
    float* out = (float*)d_out;

    cudaFuncSetAttribute(mlp_kernel, cudaFuncAttributeMaxDynamicSharedMemorySize,
                         MLP_SMEM_BYTES);

    conv_weights<<<144, 256>>>(qkv_w, proj_w, mlp_w1, mlp_w2);
    qkv_kernel<<<TOKENS / 64, 256>>>(x, ln1_scale, ln1_bias, qkv_b);
    attn_kernel<<<dim3(NWIN, HEADS), 128>>>(rpbt);
    proj_kernel<<<TOKENS / 64, 256>>>(proj_b, x);
    mlp_kernel<<<TOKENS / 64, 256, MLP_SMEM_BYTES>>>(ln2_scale, ln2_bias,
                                                     mlp_b1, mlp_b2, out);
}

// round 5
// speedup vs baseline: 1.8649x; 1.0728x over previous
#include <cuda_runtime.h>
#include <cuda_bf16.h>
#include <mma.h>
#include <cstdint>

using namespace nvcuda;

#define BATCH   8
#define HRES    256
#define WRES    256
#define CDIM    96
#define HEADS   6
#define WS      8
#define SHIFT   4
#define NWIN    8192
#define TOKENS  524288

// ---------------- Scratch ----------------
__device__ __align__(128) __nv_bfloat16 g_qkv[(size_t)TOKENS * 288];  // 302 MB
__device__ __align__(128) __nv_bfloat16 g_o  [(size_t)TOKENS * 96];   // 101 MB
__device__ __align__(128) float         g_x1 [(size_t)TOKENS * 96];   // 201 MB

// bf16 weights (converted once per launch)
__device__ __align__(128) __nv_bfloat16 g_qkvw_bf[96 * 288];
__device__ __align__(128) __nv_bfloat16 g_projw_bf[96 * 96];
__device__ __align__(128) __nv_bfloat16 g_w1_bf[96 * 384];
__device__ __align__(128) __nv_bfloat16 g_w2_bf[384 * 96];

__device__ __forceinline__ int token_to_pixel(int tw) {
    int win = tw >> 6, p = tw & 63;
    int b  = win >> 10;
    int rem = win & 1023;
    int wh = rem >> 5, ww = rem & 31;
    int hh = (wh << 3) + (p >> 3);
    int wp = (ww << 3) + (p & 7);
    int sh = (hh + SHIFT) & 255;
    int sw = (wp + SHIFT) & 255;
    return (b << 16) | (sh << 8) | sw;
}

__device__ __forceinline__ float gelu_f(float v) {
    float inner = 0.7978845608028654f * (v + 0.044715f * v * v * v);
    return 0.5f * v * (1.0f + tanhf(inner));
}

typedef wmma::fragment<wmma::matrix_a, 16, 16, 16, __nv_bfloat16, wmma::row_major> FragA;
typedef wmma::fragment<wmma::matrix_b, 16, 16, 16, __nv_bfloat16, wmma::row_major> FragB;
typedef wmma::fragment<wmma::accumulator, 16, 16, 16, float> FragC;

// pack 8 floats -> uint4 of bf16
__device__ __forceinline__ uint4 pack8_bf16(const float* v) {
    __nv_bfloat162 p0 = __floats2bfloat162_rn(v[0], v[1]);
    __nv_bfloat162 p1 = __floats2bfloat162_rn(v[2], v[3]);
    __nv_bfloat162 p2 = __floats2bfloat162_rn(v[4], v[5]);
    __nv_bfloat162 p3 = __floats2bfloat162_rn(v[6], v[7]);
    uint4 u;
    u.x = *(unsigned int*)&p0; u.y = *(unsigned int*)&p1;
    u.z = *(unsigned int*)&p2; u.w = *(unsigned int*)&p3;
    return u;
}

// =======================================================================
// Kernel 0: convert weights fp32 -> bf16
// =======================================================================
__global__ void conv_weights(const float* __restrict__ qkvw,
                             const float* __restrict__ projw,
                             const float* __restrict__ w1,
                             const float* __restrict__ w2)
{
    int i = blockIdx.x * 256 + threadIdx.x;
    if (i < 96 * 288) g_qkvw_bf[i] = __float2bfloat16(qkvw[i]);
    if (i < 96 * 96)  g_projw_bf[i] = __float2bfloat16(projw[i]);
    if (i < 96 * 384) g_w1_bf[i]   = __float2bfloat16(w1[i]);
    if (i < 384 * 96) g_w2_bf[i]   = __float2bfloat16(w2[i]);
}

// =======================================================================
// Kernel 1: LN1 + gather + QKV GEMM (bf16 HMMA, weights in smem)
// 64 tokens/block, 256 threads; dynamic smem
// =======================================================================
#define QKV_SMEM (55296 + 13312 + 10240)
__global__ __launch_bounds__(256) void qkv_kernel(
    const float* __restrict__ x, const float* __restrict__ lng,
    const float* __restrict__ lnb, const float* __restrict__ bias)
{
    extern __shared__ char smem[];
    __nv_bfloat16 (*s_w)         = (__nv_bfloat16*)smem;                 // 96*288
    __nv_bfloat16 (*s_a)[104]    = (__nv_bfloat16(*)[104])(smem + 55296);
    float         (*s_wb)[16][20]= (float(*)[16][20])(smem + 55296 + 13312);

    const int tid  = threadIdx.x;
    const int tok0 = blockIdx.x * 64;
    const int warp = tid >> 5, lane = tid & 31;

    // stage weights (27648 bf16 = 3456 uint4)
    for (int l = tid; l < 3456; l += 256)
        ((uint4*)s_w)[l] = ((const uint4*)g_qkvw_bf)[l];

    // LN direct from global (warp per token)
    for (int t = warp; t < 64; t += 8) {
        int gidx = token_to_pixel(tok0 + t);
        const float* row = &x[(size_t)gidx * 96];
        float v0 = row[lane], v1 = row[lane + 32], v2 = row[lane + 64];
        float s = v0 + v1 + v2;
        float q = v0 * v0 + v1 * v1 + v2 * v2;
        #pragma unroll
        for (int o = 16; o; o >>= 1) {
            s += __shfl_xor_sync(0xffffffffu, s, o);
            q += __shfl_xor_sync(0xffffffffu, q, o);
        }
        float mu  = s * (1.0f / 96.0f);
        float var = q * (1.0f / 96.0f) - mu * mu;
        float rs  = rsqrtf(var + 1e-5f);
        s_a[t][lane]      = __float2bfloat16((v0 - mu) * rs * lng[lane]      + lnb[lane]);
        s_a[t][lane + 32] = __float2bfloat16((v1 - mu) * rs * lng[lane + 32] + lnb[lane + 32]);
        s_a[t][lane + 64] = __float2bfloat16((v2 - mu) * rs * lng[lane + 64] + lnb[lane + 64]);
    }
    __syncthreads();

    const int mt = warp & 3, wn = warp >> 2;
    const int m0 = mt * 16;
    const int r  = lane >> 1, c0 = (lane & 1) * 8;

    for (int chunk = 0; chunk < 3; ++chunk) {
        int ntb = wn * 9 + chunk * 3;
        FragC acc[3];
        #pragma unroll
        for (int c = 0; c < 3; ++c) wmma::fill_fragment(acc[c], 0.0f);
        #pragma unroll
        for (int k = 0; k < 6; ++k) {
            FragA a;
            wmma::load_matrix_sync(a, &s_a[m0][k * 16], 104);
            #pragma unroll
            for (int c = 0; c < 3; ++c) {
                FragB b;
                wmma::load_matrix_sync(b, &s_w[(k * 16) * 288 + (ntb + c) * 16], 288);
                wmma::mma_sync(acc[c], a, b, acc[c]);
            }
        }
        #pragma unroll
        for (int c = 0; c < 3; ++c) {
            int n0 = (ntb + c) * 16;
            wmma::store_matrix_sync(&s_wb[warp][0][0], acc[c], 20, wmma::mem_row_major);
            __syncwarp();
            float* row = s_wb[warp][r];
            float v[8];
            #pragma unroll
            for (int i = 0; i < 8; ++i) v[i] = row[c0 + i] + bias[n0 + c0 + i];
            *(uint4*)&g_qkv[(size_t)(tok0 + m0 + r) * 288 + n0 + c0] = pack8_bf16(v);
            __syncwarp();
        }
    }
}

// =======================================================================
// Kernel 2: windowed attention (bf16 in/out, fp32 math)
// =======================================================================
__global__ __launch_bounds__(128) void attn_kernel(const float* __restrict__ rpbt)
{
    __shared__ float s_q[64][20], s_k[64][20], s_v[64][20];
    __shared__ float s_att[64][68];
    __shared__ int   s_reg[64];

    const int win = blockIdx.x;
    const int h   = blockIdx.y;
    const int tid = threadIdx.x;
    const int tokbase = win << 6;

    // stage q,k,v: 3 mats x 64 rows x 2 8-elem vectors
    for (int l = tid; l < 384; l += 128) {
        int mat = l >> 7;
        int rem = l & 127;
        int row = rem >> 1, h8 = rem & 1;
        uint4 u = *(const uint4*)&g_qkv[(size_t)(tokbase + row) * 288 + mat * 96 + h * 16 + h8 * 8];
        const __nv_bfloat162* p = (const __nv_bfloat162*)&u;
        float* dst = (mat == 0) ? &s_q[row][h8 * 8]
                   : (mat == 1) ? &s_k[row][h8 * 8] : &s_v[row][h8 * 8];
        float scale = (mat == 0) ? 0.25f : 1.0f;
        #pragma unroll
        for (int i = 0; i < 4; ++i) {
            float2 f = __bfloat1622float2(p[i]);
            dst[2 * i]     = f.x * scale;
            dst[2 * i + 1] = f.y * scale;
        }
    }
    if (tid < 64) {
        int rem = win & 1023;
        int wh = rem >> 5, ww = rem & 31;
        int hh = (wh << 3) + (tid >> 3);
        int wp = (ww << 3) + (tid & 7);
        int rh = (hh < 248) ? 0 : ((hh < 252) ? 1 : 2);
        int rw = (wp < 248) ? 0 : ((wp < 252) ? 1 : 2);
        s_reg[tid] = rh * 3 + rw;
    }
    __syncthreads();

    const int i    = tid >> 1;
    const int half = tid & 1;
    {
        float4 q0 = *(const float4*)&s_q[i][0];
        float4 q1 = *(const float4*)&s_q[i][4];
        float4 q2 = *(const float4*)&s_q[i][8];
        float4 q3 = *(const float4*)&s_q[i][12];
        const int regi = s_reg[i];
        const int ri = i >> 3, ci = i & 7;
        #pragma unroll 4
        for (int jo = 0; jo < 32; ++jo) {
            int jj = half * 32 + jo;
            float4 k0 = *(const float4*)&s_k[jj][0];
            float4 k1 = *(const float4*)&s_k[jj][4];
            float4 k2 = *(const float4*)&s_k[jj][8];
            float4 k3 = *(const float4*)&s_k[jj][12];
            float a = q0.x*k0.x + q0.y*k0.y + q0.z*k0.z + q0.w*k0.w
                    + q1.x*k1.x + q1.y*k1.y + q1.z*k1.z + q1.w*k1.w
                    + q2.x*k2.x + q2.y*k2.y + q2.z*k2.z + q2.w*k2.w
                    + q3.x*k3.x + q3.y*k3.y + q3.z*k3.z + q3.w*k3.w;
            int idx = ((ri - (jj >> 3) + 7) * 15 + (ci - (jj & 7) + 7));
            a += rpbt[idx * 6 + h];
            if (regi != s_reg[jj]) a -= 100.0f;
            s_att[i][jj] = a;
        }
    }
    __syncthreads();

    const int warp = tid >> 5, lane = tid & 31;
    for (int rr = 0; rr < 16; ++rr) {
        int r = warp + 4 * rr;
        float a0 = s_att[r][lane], a1 = s_att[r][lane + 32];
        float m = fmaxf(a0, a1);
        #pragma unroll
        for (int o = 16; o; o >>= 1) m = fmaxf(m, __shfl_xor_sync(0xffffffffu, m, o));
        float e0 = __expf(a0 - m), e1 = __expf(a1 - m);
        float s = e0 + e1;
        #pragma unroll
        for (int o = 16; o; o >>= 1) s += __shfl_xor_sync(0xffffffffu, s, o);
        float inv = 1.0f / s;
        s_att[r][lane]      = e0 * inv;
        s_att[r][lane + 32] = e1 * inv;
    }
    __syncthreads();

    {
        const int d0 = half * 8;
        float acc[8];
        #pragma unroll
        for (int d = 0; d < 8; ++d) acc[d] = 0.0f;
        for (int jj = 0; jj < 64; jj += 4) {
            float4 at = *(const float4*)&s_att[i][jj];
            #pragma unroll
            for (int u = 0; u < 4; ++u) {
                float a = (u == 0) ? at.x : (u == 1) ? at.y : (u == 2) ? at.z : at.w;
                float4 v0 = *(const float4*)&s_v[jj + u][d0];
                float4 v1 = *(const float4*)&s_v[jj + u][d0 + 4];
                acc[0] += a * v0.x; acc[1] += a * v0.y;
                acc[2] += a * v0.z; acc[3] += a * v0.w;
                acc[4] += a * v1.x; acc[5] += a * v1.y;
                acc[6] += a * v1.z; acc[7] += a * v1.w;
            }
        }
        *(uint4*)&g_o[(size_t)(tokbase + i) * 96 + h * 16 + d0] = pack8_bf16(acc);
    }
}

// =======================================================================
// Kernel 3: proj GEMM (weights in smem) + unshift scatter + residual
// =======================================================================
__global__ __launch_bounds__(256) void proj_kernel(
    const float* __restrict__ bias, const float* __restrict__ x)
{
    __shared__ __nv_bfloat16 s_w[96 * 96];
    __shared__ alignas(32) __nv_bfloat16 s_a[64][104];
    __shared__ alignas(32) float s_wb[8][16][20];

    const int tid  = threadIdx.x;
    const int tok0 = blockIdx.x * 64;
    const int warp = tid >> 5, lane = tid & 31;

    // stage weights (9216 bf16 = 1152 uint4)
    for (int l = tid; l < 1152; l += 256)
        ((uint4*)s_w)[l] = ((const uint4*)g_projw_bf)[l];

    // stage A from g_o (bf16 -> bf16, raw 16B copies): 64 rows x 12 uint4
    for (int l = tid; l < 768; l += 256) {
        int t = l / 12, c = l % 12;
        *(uint4*)&s_a[t][c * 8] = *(const uint4*)&g_o[(size_t)(tok0 + t) * 96 + c * 8];
    }
    __syncthreads();

    const int mt = warp & 3, wn = warp >> 2;
    const int m0 = mt * 16;
    const int r  = lane >> 1, c0 = (lane & 1) * 8;

    FragC acc[3];
    #pragma unroll
    for (int c = 0; c < 3; ++c) wmma::fill_fragment(acc[c], 0.0f);
    #pragma unroll
    for (int k = 0; k < 6; ++k) {
        FragA a;
        wmma::load_matrix_sync(a, &s_a[m0][k * 16], 104);
        #pragma unroll
        for (int c = 0; c < 3; ++c) {
            FragB b;
            wmma::load_matrix_sync(b, &s_w[(k * 16) * 96 + (wn * 3 + c) * 16], 96);
            wmma::mma_sync(acc[c], a, b, acc[c]);
        }
    }
    #pragma unroll
    for (int c = 0; c < 3; ++c) {
        int n0 = (wn * 3 + c) * 16;
        wmma::store_matrix_sync(&s_wb[warp][0][0], acc[c], 20, wmma::mem_row_major);
        __syncwarp();
        float* row = s_wb[warp][r];
        size_t gi = (size_t)token_to_pixel(tok0 + m0 + r) * 96 + n0 + c0;
        float4 xr0 = *(const float4*)&x[gi];
        float4 xr1 = *(const float4*)&x[gi + 4];
        float b0 = bias[n0 + c0],     b1 = bias[n0 + c0 + 1],
              b2 = bias[n0 + c0 + 2], b3 = bias[n0 + c0 + 3],
              b4 = bias[n0 + c0 + 4], b5 = bias[n0 + c0 + 5],
              b6 = bias[n0 + c0 + 6], b7 = bias[n0 + c0 + 7];
        *(float4*)&g_x1[gi]     = make_float4(xr0.x + row[c0] + b0,     xr0.y + row[c0 + 1] + b1,
                                              xr0.z + row[c0 + 2] + b2, xr0.w + row[c0 + 3] + b3);
        *(float4*)&g_x1[gi + 4] = make_float4(xr1.x + row[c0 + 4] + b4, xr1.y + row[c0 + 5] + b5,
                                              xr1.z + row[c0 + 6] + b6, xr1.w + row[c0 + 7] + b7);
        __syncwarp();
    }
}

// =======================================================================
// Kernel 4: LN2 + MLP1 + gelu + MLP2 + residual (weights staged in smem)
// 64 tokens/block, 256 threads
// =======================================================================
#define MLP_SMEM (73728 + 13312 + 50176 + 10240)
__global__ __launch_bounds__(256) void mlp_kernel(
    const float* __restrict__ lng, const float* __restrict__ lnb,
    const float* __restrict__ b1, const float* __restrict__ b2,
    float* __restrict__ out)
{
    extern __shared__ char smem[];
    __nv_bfloat16* s_w            = (__nv_bfloat16*)smem;                       // 73728 B
    __nv_bfloat16 (*s_a)[104]     = (__nv_bfloat16(*)[104])(smem + 73728);      // 13312 B
    __nv_bfloat16 (*s_h)[392]     = (__nv_bfloat16(*)[392])(smem + 87040);      // 50176 B
    float         (*s_wb)[16][20] = (float(*)[16][20])(smem + 137216);          // 10240 B

    const int tid  = threadIdx.x;
    const int tok0 = blockIdx.x * 64;
    const int warp = tid >> 5, lane = tid & 31;

    // stage W1 (36864 bf16 = 4608 uint4)
    for (int l = tid; l < 4608; l += 256)
        ((uint4*)s_w)[l] = ((const uint4*)g_w1_bf)[l];

    // LN2 direct from g_x1 (warp per token)
    for (int t = warp; t < 64; t += 8) {
        const float* row = &g_x1[(size_t)(tok0 + t) * 96];
        float v0 = row[lane], v1 = row[lane + 32], v2 = row[lane + 64];
        float s = v0 + v1 + v2;
        float q = v0 * v0 + v1 * v1 + v2 * v2;
        #pragma unroll
        for (int o = 16; o; o >>= 1) {
            s += __shfl_xor_sync(0xffffffffu, s, o);
            q += __shfl_xor_sync(0xffffffffu, q, o);
        }
        float mu  = s * (1.0f / 96.0f);
        float var = q * (1.0f / 96.0f) - mu * mu;
        float rs  = rsqrtf(var + 1e-5f);
        s_a[t][lane]      = __float2bfloat16((v0 - mu) * rs * lng[lane]      + lnb[lane]);
        s_a[t][lane + 32] = __float2bfloat16((v1 - mu) * rs * lng[lane + 32] + lnb[lane + 32]);
        s_a[t][lane + 64] = __float2bfloat16((v2 - mu) * rs * lng[lane + 64] + lnb[lane + 64]);
    }
    __syncthreads();

    const int mt = warp & 3, wn = warp >> 2;
    const int m0 = mt * 16;
    const int r  = lane >> 1, c0 = (lane & 1) * 8;

    // ---- MLP1 + gelu -> s_h ----
    for (int chunk = 0; chunk < 4; ++chunk) {
        int ntb = wn * 12 + chunk * 3;
        FragC acc[3];
        #pragma unroll
        for (int c = 0; c < 3; ++c) wmma::fill_fragment(acc[c], 0.0f);
        #pragma unroll
        for (int k = 0; k < 6; ++k) {
            FragA a;
            wmma::load_matrix_sync(a, &s_a[m0][k * 16], 104);
            #pragma unroll
            for (int c = 0; c < 3; ++c) {
                FragB b;
                wmma::load_matrix_sync(b, &s_w[(k * 16) * 384 + (ntb + c) * 16], 384);
                wmma::mma_sync(acc[c], a, b, acc[c]);
            }
        }
        #pragma unroll
        for (int c = 0; c < 3; ++c) {
            int n0 = (ntb + c) * 16;
            wmma::store_matrix_sync(&s_wb[warp][0][0], acc[c], 20, wmma::mem_row_major);
            __syncwarp();
            float* row = s_wb[warp][r];
            float v[8];
            #pragma unroll
            for (int i = 0; i < 8; ++i) v[i] = gelu_f(row[c0 + i] + b1[n0 + c0 + i]);
            *(uint4*)&s_h[m0 + r][n0 + c0] = pack8_bf16(v);
            __syncwarp();
        }
    }
    __syncthreads();

    // stage W2 (overwrites W1 region)
    for (int l = tid; l < 4608; l += 256)
        ((uint4*)s_w)[l] = ((const uint4*)g_w2_bf)[l];
    __syncthreads();

    // ---- MLP2 + residual ----
    {
        FragC acc[3];
        #pragma unroll
        for (int c = 0; c < 3; ++c) wmma::fill_fragment(acc[c], 0.0f);
        for (int k = 0; k < 24; ++k) {
            FragA a;
            wmma::load_matrix_sync(a, &s_h[m0][k * 16], 392);
            #pragma unroll
            for (int c = 0; c < 3; ++c) {
                FragB b;
                wmma::load_matrix_sync(b, &s_w[(k * 16) * 96 + (wn * 3 + c) * 16], 96);
                wmma::mma_sync(acc[c], a, b, acc[c]);
            }
        }
        #pragma unroll
        for (int c = 0; c < 3; ++c) {
            int n0 = (wn * 3 + c) * 16;
            wmma::store_matrix_sync(&s_wb[warp][0][0], acc[c], 20, wmma::mem_row_major);
            __syncwarp();
            float* row = s_wb[warp][r];
            size_t gi = (size_t)(tok0 + m0 + r) * 96 + n0 + c0;
            float4 x0 = *(const float4*)&g_x1[gi];
            float4 x1v = *(const float4*)&g_x1[gi + 4];
            *(float4*)&out[gi] = make_float4(
                x0.x + row[c0]     + b2[n0 + c0],
                x0.y + row[c0 + 1] + b2[n0 + c0 + 1],
                x0.z + row[c0 + 2] + b2[n0 + c0 + 2],
                x0.w + row[c0 + 3] + b2[n0 + c0 + 3]);
            *(float4*)&out[gi + 4] = make_float4(
                x1v.x + row[c0 + 4] + b2[n0 + c0 + 4],
                x1v.y + row[c0 + 5] + b2[n0 + c0 + 5],
                x1v.z + row[c0 + 6] + b2[n0 + c0 + 6],
                x1v.w + row[c0 + 7] + b2[n0 + c0 + 7]);
            __syncwarp();
        }
    }
}

// =======================================================================
extern "C" void kernel_launch(void* const* d_in, const int* in_sizes, int n_in,
                              void* d_out, int out_size)
{
    const float* x         = (const float*)d_in[0];
    const float* ln1_scale = (const float*)d_in[1];
    const float* ln1_bias  = (const float*)d_in[2];
    const float* qkv_w     = (const float*)d_in[3];
    const float* qkv_b     = (const float*)d_in[4];
    const float* rpbt      = (const float*)d_in[5];
    const float* proj_w    = (const float*)d_in[6];
    const float* proj_b    = (const float*)d_in[7];
    const float* ln2_scale = (const float*)d_in[8];
    const float* ln2_bias  = (const float*)d_in[9];
    const float* mlp_w1    = (const float*)d_in[10];
    const float* mlp_b1    = (const float*)d_in[11];
    const float* mlp_w2    = (const float*)d_in[12];
    const float* mlp_b2    = (const float*)d_in[13];
    float* out = (float*)d_out;

    cudaFuncSetAttribute(qkv_kernel, cudaFuncAttributeMaxDynamicSharedMemorySize, QKV_SMEM);
    cudaFuncSetAttribute(mlp_kernel, cudaFuncAttributeMaxDynamicSharedMemorySize, MLP_SMEM);

    conv_weights<<<144, 256>>>(qkv_w, proj_w, mlp_w1, mlp_w2);
    qkv_kernel<<<TOKENS / 64, 256, QKV_SMEM>>>(x, ln1_scale, ln1_bias, qkv_b);
    attn_kernel<<<dim3(NWIN, HEADS), 128>>>(rpbt);
    proj_kernel<<<TOKENS / 64, 256>>>(proj_b, x);
    mlp_kernel<<<TOKENS / 64, 256, MLP_SMEM>>>(ln2_scale, ln2_bias, mlp_b1, mlp_b2, out);
}

// round 6
// speedup vs baseline: 2.7243x; 1.4609x over previous
#include <cuda_runtime.h>
#include <cuda_bf16.h>
#include <mma.h>
#include <cstdint>

using namespace nvcuda;

#define BATCH   8
#define HRES    256
#define WRES    256
#define CDIM    96
#define HEADS   6
#define WS      8
#define SHIFT   4
#define NWIN    8192
#define TOKENS  524288

// ---------------- Scratch ----------------
__device__ __align__(128) __nv_bfloat16 g_qkv[(size_t)TOKENS * 288];
__device__ __align__(128) __nv_bfloat16 g_o  [(size_t)TOKENS * 96];
__device__ __align__(128) float         g_x1 [(size_t)TOKENS * 96];

__device__ __align__(128) __nv_bfloat16 g_qkvw_bf[96 * 288];
__device__ __align__(128) __nv_bfloat16 g_projw_bf[96 * 96];
__device__ __align__(128) __nv_bfloat16 g_w1_bf[96 * 384];
__device__ __align__(128) __nv_bfloat16 g_w2_bf[384 * 96];
__device__ __align__(128) float g_bias[HEADS * 64 * 64];   // rel-pos bias table

__device__ __forceinline__ int token_to_pixel(int tw) {
    int win = tw >> 6, p = tw & 63;
    int b  = win >> 10;
    int rem = win & 1023;
    int wh = rem >> 5, ww = rem & 31;
    int hh = (wh << 3) + (p >> 3);
    int wp = (ww << 3) + (p & 7);
    int sh = (hh + SHIFT) & 255;
    int sw = (wp + SHIFT) & 255;
    return (b << 16) | (sh << 8) | sw;
}

__device__ __forceinline__ float gelu_f(float v) {
    float inner = 0.7978845608028654f * (v + 0.044715f * v * v * v);
    return 0.5f * v * (1.0f + tanhf(inner));
}

typedef wmma::fragment<wmma::matrix_a, 16, 16, 16, __nv_bfloat16, wmma::row_major> FragA;
typedef wmma::fragment<wmma::matrix_b, 16, 16, 16, __nv_bfloat16, wmma::row_major> FragB;
typedef wmma::fragment<wmma::matrix_b, 16, 16, 16, __nv_bfloat16, wmma::col_major> FragBT;
typedef wmma::fragment<wmma::accumulator, 16, 16, 16, float> FragC;

__device__ __forceinline__ uint4 pack8_bf16(const float* v) {
    __nv_bfloat162 p0 = __floats2bfloat162_rn(v[0], v[1]);
    __nv_bfloat162 p1 = __floats2bfloat162_rn(v[2], v[3]);
    __nv_bfloat162 p2 = __floats2bfloat162_rn(v[4], v[5]);
    __nv_bfloat162 p3 = __floats2bfloat162_rn(v[6], v[7]);
    uint4 u;
    u.x = *(unsigned int*)&p0; u.y = *(unsigned int*)&p1;
    u.z = *(unsigned int*)&p2; u.w = *(unsigned int*)&p3;
    return u;
}

// =======================================================================
// Kernel 0: convert weights fp32->bf16 + build rel-pos bias table
// =======================================================================
__global__ void conv_weights(const float* __restrict__ qkvw,
                             const float* __restrict__ projw,
                             const float* __restrict__ w1,
                             const float* __restrict__ w2,
                             const float* __restrict__ rpbt)
{
    int i = blockIdx.x * 256 + threadIdx.x;
    if (i < 96 * 288) g_qkvw_bf[i] = __float2bfloat16(qkvw[i]);
    if (i < 96 * 96)  g_projw_bf[i] = __float2bfloat16(projw[i]);
    if (i < 96 * 384) g_w1_bf[i]   = __float2bfloat16(w1[i]);
    if (i < 384 * 96) g_w2_bf[i]   = __float2bfloat16(w2[i]);
    if (i < HEADS * 4096) {
        int h = i >> 12, r = (i >> 6) & 63, j = i & 63;
        int idx = ((r >> 3) - (j >> 3) + 7) * 15 + ((r & 7) - (j & 7) + 7);
        g_bias[i] = rpbt[idx * 6 + h];
    }
}

// =======================================================================
// Kernel 1: LN1 + gather + QKV GEMM. 64 tok/block, 256 thr.
// Warps: 2 M-groups x 4 N-groups, A cached in registers.
// =======================================================================
#define QKV_SMEM (56832 + 13312 + 10240)
__global__ __launch_bounds__(256) void qkv_kernel(
    const float* __restrict__ x, const float* __restrict__ lng,
    const float* __restrict__ lnb, const float* __restrict__ bias)
{
    extern __shared__ char smem[];
    __nv_bfloat16* s_w            = (__nv_bfloat16*)smem;                 // [96][296]
    __nv_bfloat16 (*s_a)[104]     = (__nv_bfloat16(*)[104])(smem + 56832);
    float         (*s_wb)[16][20] = (float(*)[16][20])(smem + 56832 + 13312);

    const int tid  = threadIdx.x;
    const int tok0 = blockIdx.x * 64;
    const int warp = tid >> 5, lane = tid & 31;

    // stage weights: 96 rows x 36 uint4, padded stride 296 elems
    for (int l = tid; l < 3456; l += 256) {
        int row = l / 36, c = l % 36;
        *(uint4*)&s_w[row * 296 + c * 8] = ((const uint4*)g_qkvw_bf)[l];
    }

    for (int t = warp; t < 64; t += 8) {
        int gidx = token_to_pixel(tok0 + t);
        const float* row = &x[(size_t)gidx * 96];
        float v0 = row[lane], v1 = row[lane + 32], v2 = row[lane + 64];
        float s = v0 + v1 + v2;
        float q = v0 * v0 + v1 * v1 + v2 * v2;
        #pragma unroll
        for (int o = 16; o; o >>= 1) {
            s += __shfl_xor_sync(0xffffffffu, s, o);
            q += __shfl_xor_sync(0xffffffffu, q, o);
        }
        float mu  = s * (1.0f / 96.0f);
        float var = q * (1.0f / 96.0f) - mu * mu;
        float rs  = rsqrtf(var + 1e-5f);
        s_a[t][lane]      = __float2bfloat16((v0 - mu) * rs * lng[lane]      + lnb[lane]);
        s_a[t][lane + 32] = __float2bfloat16((v1 - mu) * rs * lng[lane + 32] + lnb[lane + 32]);
        s_a[t][lane + 64] = __float2bfloat16((v2 - mu) * rs * lng[lane + 64] + lnb[lane + 64]);
    }
    __syncthreads();

    const int mg = warp & 1, wn = warp >> 1;
    const int m0 = mg * 32;
    const int r  = lane >> 1, c0 = (lane & 1) * 8;

    FragA af[2][6];
    #pragma unroll
    for (int mi = 0; mi < 2; ++mi)
        #pragma unroll
        for (int k = 0; k < 6; ++k)
            wmma::load_matrix_sync(af[mi][k], &s_a[m0 + mi * 16][k * 16], 104);

    for (int nt = wn; nt < 18; nt += 4) {
        FragC acc0, acc1;
        wmma::fill_fragment(acc0, 0.0f);
        wmma::fill_fragment(acc1, 0.0f);
        #pragma unroll
        for (int k = 0; k < 6; ++k) {
            FragB b;
            wmma::load_matrix_sync(b, &s_w[(k * 16) * 296 + nt * 16], 296);
            wmma::mma_sync(acc0, af[0][k], b, acc0);
            wmma::mma_sync(acc1, af[1][k], b, acc1);
        }
        int n0 = nt * 16;
        #pragma unroll
        for (int mi = 0; mi < 2; ++mi) {
            wmma::store_matrix_sync(&s_wb[warp][0][0], mi ? acc1 : acc0, 20, wmma::mem_row_major);
            __syncwarp();
            float* row = s_wb[warp][r];
            float v[8];
            #pragma unroll
            for (int i = 0; i < 8; ++i) v[i] = row[c0 + i] + bias[n0 + c0 + i];
            *(uint4*)&g_qkv[(size_t)(tok0 + m0 + mi * 16 + r) * 288 + n0 + c0] = pack8_bf16(v);
            __syncwarp();
        }
    }
}

// =======================================================================
// Kernel 2: windowed attention via wmma. grid (NWIN, HEADS), 128 thr (4 warps).
// =======================================================================
__global__ __launch_bounds__(128) void attn_kernel()
{
    __shared__ __nv_bfloat16 s_q[64][24], s_k[64][24], s_v[64][24];
    __shared__ float s_att[64][72];
    __shared__ __nv_bfloat16 s_p[64][72];
    __shared__ int s_reg[64];

    const int win = blockIdx.x;
    const int h   = blockIdx.y;
    const int tid = threadIdx.x;
    const int warp = tid >> 5, lane = tid & 31;
    const int tokbase = win << 6;

    // stage q,k,v head slices (bf16 raw 16B copies)
    for (int l = tid; l < 384; l += 128) {
        int mat = l >> 7;
        int rem = l & 127;
        int row = rem >> 1, half = rem & 1;
        uint4 u = *(const uint4*)&g_qkv[(size_t)(tokbase + row) * 288 + mat * 96 + h * 16 + half * 8];
        if (mat == 0)      *(uint4*)&s_q[row][half * 8] = u;
        else if (mat == 1) *(uint4*)&s_k[row][half * 8] = u;
        else               *(uint4*)&s_v[row][half * 8] = u;
    }
    int remw = win & 1023;
    int wh = remw >> 5, ww = remw & 31;
    bool boundary = (wh == 31) || (ww == 31);
    if (tid < 64) {
        int hh = (wh << 3) + (tid >> 3);
        int wp = (ww << 3) + (tid & 7);
        int rh = (hh < 248) ? 0 : ((hh < 252) ? 1 : 2);
        int rw = (wp < 248) ? 0 : ((wp < 252) ? 1 : 2);
        s_reg[tid] = rh * 3 + rw;
    }
    __syncthreads();

    // ---- QK^T (each warp: one 16-row block x all 64 cols) ----
    {
        const int m0 = warp * 16;
        FragA a;
        wmma::load_matrix_sync(a, &s_q[m0][0], 24);
        #pragma unroll
        for (int c = 0; c < 4; ++c) {
            FragBT b;
            wmma::load_matrix_sync(b, &s_k[c * 16][0], 24);
            FragC acc;
            wmma::fill_fragment(acc, 0.0f);
            wmma::mma_sync(acc, a, b, acc);
            #pragma unroll
            for (int t = 0; t < acc.num_elements; ++t) acc.x[t] *= 0.25f;
            wmma::store_matrix_sync(&s_att[m0][c * 16], acc, 72, wmma::mem_row_major);
        }
    }
    __syncthreads();

    // ---- softmax (+ bias + mask), output bf16 probs ----
    {
        const float* btab = &g_bias[h << 12];
        for (int rr = 0; rr < 16; ++rr) {
            int r = warp * 16 + rr;
            float a0 = s_att[r][lane]      + btab[(r << 6) + lane];
            float a1 = s_att[r][lane + 32] + btab[(r << 6) + lane + 32];
            if (boundary) {
                int ri = s_reg[r];
                if (ri != s_reg[lane])      a0 -= 100.0f;
                if (ri != s_reg[lane + 32]) a1 -= 100.0f;
            }
            float m = fmaxf(a0, a1);
            #pragma unroll
            for (int o = 16; o; o >>= 1) m = fmaxf(m, __shfl_xor_sync(0xffffffffu, m, o));
            float e0 = __expf(a0 - m), e1 = __expf(a1 - m);
            float s = e0 + e1;
            #pragma unroll
            for (int o = 16; o; o >>= 1) s += __shfl_xor_sync(0xffffffffu, s, o);
            float inv = 1.0f / s;
            s_p[r][lane]      = __float2bfloat16(e0 * inv);
            s_p[r][lane + 32] = __float2bfloat16(e1 * inv);
        }
    }
    __syncthreads();

    // ---- o = P @ V ----
    {
        const int m0 = warp * 16;
        FragC acc;
        wmma::fill_fragment(acc, 0.0f);
        #pragma unroll
        for (int kc = 0; kc < 4; ++kc) {
            FragA a;
            wmma::load_matrix_sync(a, &s_p[m0][kc * 16], 72);
            FragB b;
            wmma::load_matrix_sync(b, &s_v[kc * 16][0], 24);
            wmma::mma_sync(acc, a, b, acc);
        }
        wmma::store_matrix_sync(&s_att[m0][0], acc, 72, wmma::mem_row_major);
        __syncwarp();
        const int r = lane >> 1, c0 = (lane & 1) * 8;
        float v[8];
        #pragma unroll
        for (int i = 0; i < 8; ++i) v[i] = s_att[m0 + r][c0 + i];
        *(uint4*)&g_o[(size_t)(tokbase + m0 + r) * 96 + h * 16 + c0] = pack8_bf16(v);
    }
}

// =======================================================================
// Kernel 3: proj GEMM + unshift scatter + residual (padded weight stride)
// =======================================================================
__global__ __launch_bounds__(256) void proj_kernel(
    const float* __restrict__ bias, const float* __restrict__ x)
{
    __shared__ __nv_bfloat16 s_w[96][104];
    __shared__ alignas(32) __nv_bfloat16 s_a[64][104];
    __shared__ alignas(32) float s_wb[8][16][20];

    const int tid  = threadIdx.x;
    const int tok0 = blockIdx.x * 64;
    const int warp = tid >> 5, lane = tid & 31;

    for (int l = tid; l < 1152; l += 256) {
        int row = l / 12, c = l % 12;
        *(uint4*)&s_w[row][c * 8] = ((const uint4*)g_projw_bf)[l];
    }
    for (int l = tid; l < 768; l += 256) {
        int t = l / 12, c = l % 12;
        *(uint4*)&s_a[t][c * 8] = *(const uint4*)&g_o[(size_t)(tok0 + t) * 96 + c * 8];
    }
    __syncthreads();

    const int mg = warp & 1, wn = warp >> 1;
    const int m0 = mg * 32;
    const int r  = lane >> 1, c0 = (lane & 1) * 8;

    FragA af[2][6];
    #pragma unroll
    for (int mi = 0; mi < 2; ++mi)
        #pragma unroll
        for (int k = 0; k < 6; ++k)
            wmma::load_matrix_sync(af[mi][k], &s_a[m0 + mi * 16][k * 16], 104);

    for (int nt = wn; nt < 6; nt += 4) {
        FragC acc0, acc1;
        wmma::fill_fragment(acc0, 0.0f);
        wmma::fill_fragment(acc1, 0.0f);
        #pragma unroll
        for (int k = 0; k < 6; ++k) {
            FragB b;
            wmma::load_matrix_sync(b, &s_w[k * 16][nt * 16], 104);
            wmma::mma_sync(acc0, af[0][k], b, acc0);
            wmma::mma_sync(acc1, af[1][k], b, acc1);
        }
        int n0 = nt * 16;
        #pragma unroll
        for (int mi = 0; mi < 2; ++mi) {
            wmma::store_matrix_sync(&s_wb[warp][0][0], mi ? acc1 : acc0, 20, wmma::mem_row_major);
            __syncwarp();
            float* row = s_wb[warp][r];
            size_t gi = (size_t)token_to_pixel(tok0 + m0 + mi * 16 + r) * 96 + n0 + c0;
            float4 x0 = *(const float4*)&x[gi];
            float4 x1v = *(const float4*)&x[gi + 4];
            *(float4*)&g_x1[gi] = make_float4(
                x0.x + row[c0]     + bias[n0 + c0],
                x0.y + row[c0 + 1] + bias[n0 + c0 + 1],
                x0.z + row[c0 + 2] + bias[n0 + c0 + 2],
                x0.w + row[c0 + 3] + bias[n0 + c0 + 3]);
            *(float4*)&g_x1[gi + 4] = make_float4(
                x1v.x + row[c0 + 4] + bias[n0 + c0 + 4],
                x1v.y + row[c0 + 5] + bias[n0 + c0 + 5],
                x1v.z + row[c0 + 6] + bias[n0 + c0 + 6],
                x1v.w + row[c0 + 7] + bias[n0 + c0 + 7]);
            __syncwarp();
        }
    }
}

// =======================================================================
// Kernel 4: LN2 + MLP1 + gelu + MLP2 + residual
// =======================================================================
#define MLP_SMEM (79872 + 13312 + 50176 + 10240)
__global__ __launch_bounds__(256) void mlp_kernel(
    const float* __restrict__ lng, const float* __restrict__ lnb,
    const float* __restrict__ b1, const float* __restrict__ b2,
    float* __restrict__ out)
{
    extern __shared__ char smem[];
    __nv_bfloat16* s_w            = (__nv_bfloat16*)smem;                    // W1 [96][392] / W2 [384][104]
    __nv_bfloat16 (*s_a)[104]     = (__nv_bfloat16(*)[104])(smem + 79872);
    __nv_bfloat16 (*s_h)[392]     = (__nv_bfloat16(*)[392])(smem + 93184);
    float         (*s_wb)[16][20] = (float(*)[16][20])(smem + 143360);

    const int tid  = threadIdx.x;
    const int tok0 = blockIdx.x * 64;
    const int warp = tid >> 5, lane = tid & 31;

    // stage W1: 96 rows x 48 uint4, stride 392
    for (int l = tid; l < 4608; l += 256) {
        int row = l / 48, c = l % 48;
        *(uint4*)&s_w[row * 392 + c * 8] = ((const uint4*)g_w1_bf)[l];
    }

    for (int t = warp; t < 64; t += 8) {
        const float* row = &g_x1[(size_t)(tok0 + t) * 96];
        float v0 = row[lane], v1 = row[lane + 32], v2 = row[lane + 64];
        float s = v0 + v1 + v2;
        float q = v0 * v0 + v1 * v1 + v2 * v2;
        #pragma unroll
        for (int o = 16; o; o >>= 1) {
            s += __shfl_xor_sync(0xffffffffu, s, o);
            q += __shfl_xor_sync(0xffffffffu, q, o);
        }
        float mu  = s * (1.0f / 96.0f);
        float var = q * (1.0f / 96.0f) - mu * mu;
        float rs  = rsqrtf(var + 1e-5f);
        s_a[t][lane]      = __float2bfloat16((v0 - mu) * rs * lng[lane]      + lnb[lane]);
        s_a[t][lane + 32] = __float2bfloat16((v1 - mu) * rs * lng[lane + 32] + lnb[lane + 32]);
        s_a[t][lane + 64] = __float2bfloat16((v2 - mu) * rs * lng[lane + 64] + lnb[lane + 64]);
    }
    __syncthreads();

    const int mg = warp & 1, wn = warp >> 1;
    const int m0g = mg * 32;
    const int r  = lane >> 1, c0 = (lane & 1) * 8;

    // ---- MLP1 + gelu -> s_h (A cached in regs) ----
    {
        FragA af[2][6];
        #pragma unroll
        for (int mi = 0; mi < 2; ++mi)
            #pragma unroll
            for (int k = 0; k < 6; ++k)
                wmma::load_matrix_sync(af[mi][k], &s_a[m0g + mi * 16][k * 16], 104);

        for (int nt = wn; nt < 24; nt += 4) {
            FragC acc0, acc1;
            wmma::fill_fragment(acc0, 0.0f);
            wmma::fill_fragment(acc1, 0.0f);
            #pragma unroll
            for (int k = 0; k < 6; ++k) {
                FragB b;
                wmma::load_matrix_sync(b, &s_w[(k * 16) * 392 + nt * 16], 392);
                wmma::mma_sync(acc0, af[0][k], b, acc0);
                wmma::mma_sync(acc1, af[1][k], b, acc1);
            }
            int n0 = nt * 16;
            #pragma unroll
            for (int mi = 0; mi < 2; ++mi) {
                wmma::store_matrix_sync(&s_wb[warp][0][0], mi ? acc1 : acc0, 20, wmma::mem_row_major);
                __syncwarp();
                float* row = s_wb[warp][r];
                float v[8];
                #pragma unroll
                for (int i = 0; i < 8; ++i) v[i] = gelu_f(row[c0 + i] + b1[n0 + c0 + i]);
                *(uint4*)&s_h[m0g + mi * 16 + r][n0 + c0] = pack8_bf16(v);
                __syncwarp();
            }
        }
    }
    __syncthreads();

    // stage W2: 384 rows x 12 uint4, stride 104
    for (int l = tid; l < 4608; l += 256) {
        int row = l / 12, c = l % 12;
        *(uint4*)&s_w[row * 104 + c * 8] = ((const uint4*)g_w2_bf)[l];
    }
    __syncthreads();

    // ---- MLP2 + residual (k-outer, FragC live) ----
    {
        const int mt = warp & 3, wn2 = warp >> 2;
        const int m0 = mt * 16;
        FragC acc[3];
        #pragma unroll
        for (int c = 0; c < 3; ++c) wmma::fill_fragment(acc[c], 0.0f);
        for (int k = 0; k < 24; ++k) {
            FragA a;
            wmma::load_matrix_sync(a, &s_h[m0][k * 16], 392);
            #pragma unroll
            for (int c = 0; c < 3; ++c) {
                FragB b;
                wmma::load_matrix_sync(b, &s_w[(k * 16) * 104 + (wn2 * 3 + c) * 16], 104);
                wmma::mma_sync(acc[c], a, b, acc[c]);
            }
        }
        #pragma unroll
        for (int c = 0; c < 3; ++c) {
            int n0 = (wn2 * 3 + c) * 16;
            wmma::store_matrix_sync(&s_wb[warp][0][0], acc[c], 20, wmma::mem_row_major);
            __syncwarp();
            float* row = s_wb[warp][r];
            size_t gi = (size_t)(tok0 + m0 + r) * 96 + n0 + c0;
            float4 x0 = *(const float4*)&g_x1[gi];
            float4 x1v = *(const float4*)&g_x1[gi + 4];
            *(float4*)&out[gi] = make_float4(
                x0.x + row[c0]     + b2[n0 + c0],
                x0.y + row[c0 + 1] + b2[n0 + c0 + 1],
                x0.z + row[c0 + 2] + b2[n0 + c0 + 2],
                x0.w + row[c0 + 3] + b2[n0 + c0 + 3]);
            *(float4*)&out[gi + 4] = make_float4(
                x1v.x + row[c0 + 4] + b2[n0 + c0 + 4],
                x1v.y + row[c0 + 5] + b2[n0 + c0 + 5],
                x1v.z + row[c0 + 6] + b2[n0 + c0 + 6],
                x1v.w + row[c0 + 7] + b2[n0 + c0 + 7]);
            __syncwarp();
        }
    }
}

// =======================================================================
extern "C" void kernel_launch(void* const* d_in, const int* in_sizes, int n_in,
                              void* d_out, int out_size)
{
    const float* x         = (const float*)d_in[0];
    const float* ln1_scale = (const float*)d_in[1];
    const float* ln1_bias  = (const float*)d_in[2];
    const float* qkv_w     = (const float*)d_in[3];
    const float* qkv_b     = (const float*)d_in[4];
    const float* rpbt      = (const float*)d_in[5];
    const float* proj_w    = (const float*)d_in[6];
    const float* proj_b    = (const float*)d_in[7];
    const float* ln2_scale = (const float*)d_in[8];
    const float* ln2_bias  = (const float*)d_in[9];
    const float* mlp_w1    = (const float*)d_in[10];
    const float* mlp_b1    = (const float*)d_in[11];
    const float* mlp_w2    = (const float*)d_in[12];
    const float* mlp_b2    = (const float*)d_in[13];
    float* out = (float*)d_out;

    cudaFuncSetAttribute(qkv_kernel, cudaFuncAttributeMaxDynamicSharedMemorySize, QKV_SMEM);
    cudaFuncSetAttribute(mlp_kernel, cudaFuncAttributeMaxDynamicSharedMemorySize, MLP_SMEM);

    conv_weights<<<144, 256>>>(qkv_w, proj_w, mlp_w1, mlp_w2, rpbt);
    qkv_kernel<<<TOKENS / 64, 256, QKV_SMEM>>>(x, ln1_scale, ln1_bias, qkv_b);
    attn_kernel<<<dim3(NWIN, HEADS), 128>>>();
    proj_kernel<<<TOKENS / 64, 256>>>(proj_b, x);
    mlp_kernel<<<TOKENS / 64, 256, MLP_SMEM>>>(ln2_scale, ln2_bias, mlp_b1, mlp_b2, out);
}

// round 7
// speedup vs baseline: 3.0994x; 1.1377x over previous
#include <cuda_runtime.h>
#include <cuda_bf16.h>
#include <mma.h>
#include <cstdint>

using namespace nvcuda;

#define BATCH   8
#define HRES    256
#define WRES    256
#define CDIM    96
#define HEADS   6
#define WS      8
#define SHIFT   4
#define NWIN    8192
#define TOKENS  524288

// ---------------- Scratch ----------------
__device__ __align__(128) float g_x1[(size_t)TOKENS * 96];

__device__ __align__(128) __nv_bfloat16 g_qkvw_bf[96 * 288];
__device__ __align__(128) __nv_bfloat16 g_projw_bf[96 * 96];
__device__ __align__(128) __nv_bfloat16 g_w1_bf[96 * 384];
__device__ __align__(128) __nv_bfloat16 g_w2_bf[384 * 96];
__device__ __align__(128) float g_bias[HEADS * 64 * 64];

__device__ __forceinline__ int token_to_pixel(int tw) {
    int win = tw >> 6, p = tw & 63;
    int b  = win >> 10;
    int rem = win & 1023;
    int wh = rem >> 5, ww = rem & 31;
    int hh = (wh << 3) + (p >> 3);
    int wp = (ww << 3) + (p & 7);
    int sh = (hh + SHIFT) & 255;
    int sw = (wp + SHIFT) & 255;
    return (b << 16) | (sh << 8) | sw;
}

__device__ __forceinline__ float gelu_f(float v) {
    float inner = 0.7978845608028654f * (v + 0.044715f * v * v * v);
    return 0.5f * v * (1.0f + tanhf(inner));
}

typedef wmma::fragment<wmma::matrix_a, 16, 16, 16, __nv_bfloat16, wmma::row_major> FragA;
typedef wmma::fragment<wmma::matrix_b, 16, 16, 16, __nv_bfloat16, wmma::row_major> FragB;
typedef wmma::fragment<wmma::matrix_b, 16, 16, 16, __nv_bfloat16, wmma::col_major> FragBT;
typedef wmma::fragment<wmma::accumulator, 16, 16, 16, float> FragC;

__device__ __forceinline__ uint4 pack8_bf16(const float* v) {
    __nv_bfloat162 p0 = __floats2bfloat162_rn(v[0], v[1]);
    __nv_bfloat162 p1 = __floats2bfloat162_rn(v[2], v[3]);
    __nv_bfloat162 p2 = __floats2bfloat162_rn(v[4], v[5]);
    __nv_bfloat162 p3 = __floats2bfloat162_rn(v[6], v[7]);
    uint4 u;
    u.x = *(unsigned int*)&p0; u.y = *(unsigned int*)&p1;
    u.z = *(unsigned int*)&p2; u.w = *(unsigned int*)&p3;
    return u;
}

// =======================================================================
// Kernel 0: convert weights + rel-pos bias table
// =======================================================================
__global__ void conv_weights(const float* __restrict__ qkvw,
                             const float* __restrict__ projw,
                             const float* __restrict__ w1,
                             const float* __restrict__ w2,
                             const float* __restrict__ rpbt)
{
    int i = blockIdx.x * 256 + threadIdx.x;
    if (i < 96 * 288) g_qkvw_bf[i] = __float2bfloat16(qkvw[i]);
    if (i < 96 * 96)  g_projw_bf[i] = __float2bfloat16(projw[i]);
    if (i < 96 * 384) g_w1_bf[i]   = __float2bfloat16(w1[i]);
    if (i < 384 * 96) g_w2_bf[i]   = __float2bfloat16(w2[i]);
    if (i < HEADS * 4096) {
        int h = i >> 12, r = (i >> 6) & 63, j = i & 63;
        int idx = ((r >> 3) - (j >> 3) + 7) * 15 + ((r & 7) - (j & 7) + 7);
        g_bias[i] = rpbt[idx * 6 + h];
    }
}

// =======================================================================
// MEGA kernel: LN1 + QKV + attention(6 heads) + proj + scatter + residual
// 1 block = 1 window (64 tokens), 384 threads (12 warps)
// =======================================================================
#define MEGA_SMEM 206592
__global__ __launch_bounds__(384) void mega_kernel(
    const float* __restrict__ x, const float* __restrict__ lng,
    const float* __restrict__ lnb, const float* __restrict__ qkvb,
    const float* __restrict__ projb)
{
    extern __shared__ char smem[];
    __nv_bfloat16* s_w             = (__nv_bfloat16*)smem;                     // qkvW [96][296] / projW [96][104]
    __nv_bfloat16 (*s_qkv)[296]    = (__nv_bfloat16(*)[296])(smem + 56832);    // 37888
    __nv_bfloat16 (*s_ao)[104]     = (__nv_bfloat16(*)[104])(smem + 94720);    // 13312 (LN out, then o)
    float         (*s_att)[16][72] = (float(*)[16][72])(smem + 108032);        // 55296
    __nv_bfloat16 (*s_p)[16][72]   = (__nv_bfloat16(*)[16][72])(smem + 163328);// 27648
    float         (*s_wb)[16][20]  = (float(*)[16][20])(smem + 190976);        // 15360
    int*           s_reg           = (int*)(smem + 206336);                    // 256

    const int tid  = threadIdx.x;
    const int win  = blockIdx.x;
    const int tok0 = win << 6;
    const int warp = tid >> 5, lane = tid & 31;

    // stage QKV weights: 96 rows x 36 uint4, stride 296
    for (int l = tid; l < 3456; l += 384) {
        int row = l / 36, c = l % 36;
        *(uint4*)&s_w[row * 296 + c * 8] = ((const uint4*)g_qkvw_bf)[l];
    }

    const int remw = win & 1023;
    const int wh = remw >> 5, ww = remw & 31;
    const bool boundary = (wh == 31) || (ww == 31);
    if (tid < 64) {
        int hh = (wh << 3) + (tid >> 3);
        int wp = (ww << 3) + (tid & 7);
        int rh = (hh < 248) ? 0 : ((hh < 252) ? 1 : 2);
        int rw = (wp < 248) ? 0 : ((wp < 252) ? 1 : 2);
        s_reg[tid] = rh * 3 + rw;
    }

    // LN1 (warp per token)
    for (int t = warp; t < 64; t += 12) {
        int gidx = token_to_pixel(tok0 + t);
        const float* row = &x[(size_t)gidx * 96];
        float v0 = row[lane], v1 = row[lane + 32], v2 = row[lane + 64];
        float s = v0 + v1 + v2;
        float q = v0 * v0 + v1 * v1 + v2 * v2;
        #pragma unroll
        for (int o = 16; o; o >>= 1) {
            s += __shfl_xor_sync(0xffffffffu, s, o);
            q += __shfl_xor_sync(0xffffffffu, q, o);
        }
        float mu  = s * (1.0f / 96.0f);
        float var = q * (1.0f / 96.0f) - mu * mu;
        float rs  = rsqrtf(var + 1e-5f);
        s_ao[t][lane]      = __float2bfloat16((v0 - mu) * rs * lng[lane]      + lnb[lane]);
        s_ao[t][lane + 32] = __float2bfloat16((v1 - mu) * rs * lng[lane + 32] + lnb[lane + 32]);
        s_ao[t][lane + 64] = __float2bfloat16((v2 - mu) * rs * lng[lane + 64] + lnb[lane + 64]);
    }
    __syncthreads();

    const int r  = lane >> 1, c0 = (lane & 1) * 8;

    // ---- QKV GEMM: warps = 4 m-tiles x 3 n-groups (6 n-tiles each) ----
    {
        const int mg = warp & 3, wn = warp >> 2;
        const int m0 = mg * 16;
        FragA af[6];
        #pragma unroll
        for (int k = 0; k < 6; ++k)
            wmma::load_matrix_sync(af[k], &s_ao[m0][k * 16], 104);
        for (int nt = wn * 6; nt < wn * 6 + 6; ++nt) {
            FragC acc;
            wmma::fill_fragment(acc, 0.0f);
            #pragma unroll
            for (int k = 0; k < 6; ++k) {
                FragB b;
                wmma::load_matrix_sync(b, &s_w[(k * 16) * 296 + nt * 16], 296);
                wmma::mma_sync(acc, af[k], b, acc);
            }
            wmma::store_matrix_sync(&s_wb[warp][0][0], acc, 20, wmma::mem_row_major);
            __syncwarp();
            int n0 = nt * 16;
            float v[8];
            float scale = (n0 < 96) ? 0.25f : 1.0f;   // fold q scaling
            #pragma unroll
            for (int i = 0; i < 8; ++i)
                v[i] = (s_wb[warp][r][c0 + i] + qkvb[n0 + c0 + i]) * scale;
            *(uint4*)&s_qkv[m0 + r][n0 + c0] = pack8_bf16(v);
            __syncwarp();
        }
    }
    __syncthreads();

    // ---- attention: 24 units (6 heads x 4 m-tiles) over 12 warps ----
    for (int u = warp; u < 24; u += 12) {
        const int h = u >> 2, mt = u & 3;
        const int m0 = mt * 16;
        // QK^T with rel-pos bias preloaded as C
        {
            FragA a;
            wmma::load_matrix_sync(a, &s_qkv[m0][h * 16], 296);
            #pragma unroll
            for (int c = 0; c < 4; ++c) {
                FragC acc;
                wmma::load_matrix_sync(acc, &g_bias[(h << 12) + m0 * 64 + c * 16], 64,
                                       wmma::mem_row_major);
                FragBT bt;
                wmma::load_matrix_sync(bt, &s_qkv[c * 16][96 + h * 16], 296);
                wmma::mma_sync(acc, a, bt, acc);
                wmma::store_matrix_sync(&s_att[warp][0][c * 16], acc, 72, wmma::mem_row_major);
            }
        }
        __syncwarp();
        // softmax (16 rows)
        for (int rr = 0; rr < 16; ++rr) {
            float a0 = s_att[warp][rr][lane];
            float a1 = s_att[warp][rr][lane + 32];
            if (boundary) {
                int ri = s_reg[m0 + rr];
                if (ri != s_reg[lane])      a0 -= 100.0f;
                if (ri != s_reg[lane + 32]) a1 -= 100.0f;
            }
            float m = fmaxf(a0, a1);
            #pragma unroll
            for (int o = 16; o; o >>= 1) m = fmaxf(m, __shfl_xor_sync(0xffffffffu, m, o));
            float e0 = __expf(a0 - m), e1 = __expf(a1 - m);
            float s = e0 + e1;
            #pragma unroll
            for (int o = 16; o; o >>= 1) s += __shfl_xor_sync(0xffffffffu, s, o);
            float inv = 1.0f / s;
            s_p[warp][rr][lane]      = __float2bfloat16(e0 * inv);
            s_p[warp][rr][lane + 32] = __float2bfloat16(e1 * inv);
        }
        __syncwarp();
        // o = P @ V
        {
            FragC acc;
            wmma::fill_fragment(acc, 0.0f);
            #pragma unroll
            for (int kc = 0; kc < 4; ++kc) {
                FragA ap;
                wmma::load_matrix_sync(ap, &s_p[warp][0][kc * 16], 72);
                FragB bv;
                wmma::load_matrix_sync(bv, &s_qkv[kc * 16][192 + h * 16], 296);
                wmma::mma_sync(acc, ap, bv, acc);
            }
            wmma::store_matrix_sync(&s_att[warp][0][0], acc, 72, wmma::mem_row_major);
            __syncwarp();
            float v[8];
            #pragma unroll
            for (int i = 0; i < 8; ++i) v[i] = s_att[warp][r][c0 + i];
            *(uint4*)&s_ao[m0 + r][h * 16 + c0] = pack8_bf16(v);
        }
        __syncwarp();
    }
    __syncthreads();

    // stage proj weights [96][104]
    for (int l = tid; l < 1152; l += 384) {
        int row = l / 12, c = l % 12;
        *(uint4*)&s_w[row * 104 + c * 8] = ((const uint4*)g_projw_bf)[l];
    }
    __syncthreads();

    // ---- proj + scatter + residual: 4 m-tiles x 3 n-groups (2 n-tiles each) ----
    {
        const int mg = warp & 3, wn = warp >> 2;
        const int m0 = mg * 16;
        FragA af[6];
        #pragma unroll
        for (int k = 0; k < 6; ++k)
            wmma::load_matrix_sync(af[k], &s_ao[m0][k * 16], 104);
        for (int nt = wn * 2; nt < wn * 2 + 2; ++nt) {
            FragC acc;
            wmma::fill_fragment(acc, 0.0f);
            #pragma unroll
            for (int k = 0; k < 6; ++k) {
                FragB b;
                wmma::load_matrix_sync(b, &s_w[(k * 16) * 104 + nt * 16], 104);
                wmma::mma_sync(acc, af[k], b, acc);
            }
            wmma::store_matrix_sync(&s_wb[warp][0][0], acc, 20, wmma::mem_row_major);
            __syncwarp();
            int n0 = nt * 16;
            size_t gi = (size_t)token_to_pixel(tok0 + m0 + r) * 96 + n0 + c0;
            float4 x0 = *(const float4*)&x[gi];
            float4 x1v = *(const float4*)&x[gi + 4];
            float* row = s_wb[warp][r];
            *(float4*)&g_x1[gi] = make_float4(
                x0.x + row[c0]     + projb[n0 + c0],
                x0.y + row[c0 + 1] + projb[n0 + c0 + 1],
                x0.z + row[c0 + 2] + projb[n0 + c0 + 2],
                x0.w + row[c0 + 3] + projb[n0 + c0 + 3]);
            *(float4*)&g_x1[gi + 4] = make_float4(
                x1v.x + row[c0 + 4] + projb[n0 + c0 + 4],
                x1v.y + row[c0 + 5] + projb[n0 + c0 + 5],
                x1v.z + row[c0 + 6] + projb[n0 + c0 + 6],
                x1v.w + row[c0 + 7] + projb[n0 + c0 + 7]);
            __syncwarp();
        }
    }
}

// =======================================================================
// Kernel 2: LN2 + MLP1 + gelu + MLP2 + residual. 128 tok/block, 384 thr.
// =======================================================================
#define MLP_SMEM 222208
__global__ __launch_bounds__(384) void mlp_kernel(
    const float* __restrict__ lng, const float* __restrict__ lnb,
    const float* __restrict__ b1, const float* __restrict__ b2,
    float* __restrict__ out)
{
    extern __shared__ char smem[];
    __nv_bfloat16* s_w            = (__nv_bfloat16*)smem;                      // W1 [96][392] / W2 [384][104]
    __nv_bfloat16 (*s_a)[104]     = (__nv_bfloat16(*)[104])(smem + 79872);     // 26624
    __nv_bfloat16 (*s_h)[392]     = (__nv_bfloat16(*)[392])(smem + 106496);    // 100352
    float         (*s_wb)[16][20] = (float(*)[16][20])(smem + 206848);         // 15360

    const int tid  = threadIdx.x;
    const int tok0 = blockIdx.x * 128;
    const int warp = tid >> 5, lane = tid & 31;

    // stage W1: 96 rows x 48 uint4, stride 392
    for (int l = tid; l < 4608; l += 384) {
        int row = l / 48, c = l % 48;
        *(uint4*)&s_w[row * 392 + c * 8] = ((const uint4*)g_w1_bf)[l];
    }

    for (int t = warp; t < 128; t += 12) {
        const float* row = &g_x1[(size_t)(tok0 + t) * 96];
        float v0 = row[lane], v1 = row[lane + 32], v2 = row[lane + 64];
        float s = v0 + v1 + v2;
        float q = v0 * v0 + v1 * v1 + v2 * v2;
        #pragma unroll
        for (int o = 16; o; o >>= 1) {
            s += __shfl_xor_sync(0xffffffffu, s, o);
            q += __shfl_xor_sync(0xffffffffu, q, o);
        }
        float mu  = s * (1.0f / 96.0f);
        float var = q * (1.0f / 96.0f) - mu * mu;
        float rs  = rsqrtf(var + 1e-5f);
        s_a[t][lane]      = __float2bfloat16((v0 - mu) * rs * lng[lane]      + lnb[lane]);
        s_a[t][lane + 32] = __float2bfloat16((v1 - mu) * rs * lng[lane + 32] + lnb[lane + 32]);
        s_a[t][lane + 64] = __float2bfloat16((v2 - mu) * rs * lng[lane + 64] + lnb[lane + 64]);
    }
    __syncthreads();

    const int r  = lane >> 1, c0 = (lane & 1) * 8;
    const int mg = warp & 3, wn = warp >> 2;
    const int m0g = mg * 32;

    // ---- MLP1 + gelu -> s_h ----
    {
        FragA af[2][6];
        #pragma unroll
        for (int mi = 0; mi < 2; ++mi)
            #pragma unroll
            for (int k = 0; k < 6; ++k)
                wmma::load_matrix_sync(af[mi][k], &s_a[m0g + mi * 16][k * 16], 104);

        for (int nt = wn; nt < 24; nt += 3) {
            FragC acc0, acc1;
            wmma::fill_fragment(acc0, 0.0f);
            wmma::fill_fragment(acc1, 0.0f);
            #pragma unroll
            for (int k = 0; k < 6; ++k) {
                FragB b;
                wmma::load_matrix_sync(b, &s_w[(k * 16) * 392 + nt * 16], 392);
                wmma::mma_sync(acc0, af[0][k], b, acc0);
                wmma::mma_sync(acc1, af[1][k], b, acc1);
            }
            int n0 = nt * 16;
            #pragma unroll
            for (int mi = 0; mi < 2; ++mi) {
                wmma::store_matrix_sync(&s_wb[warp][0][0], mi ? acc1 : acc0, 20,
                                        wmma::mem_row_major);
                __syncwarp();
                float v[8];
                #pragma unroll
                for (int i = 0; i < 8; ++i)
                    v[i] = gelu_f(s_wb[warp][r][c0 + i] + b1[n0 + c0 + i]);
                *(uint4*)&s_h[m0g + mi * 16 + r][n0 + c0] = pack8_bf16(v);
                __syncwarp();
            }
        }
    }
    __syncthreads();

    // stage W2: 384 rows x 12 uint4, stride 104
    for (int l = tid; l < 4608; l += 384) {
        int row = l / 12, c = l % 12;
        *(uint4*)&s_w[row * 104 + c * 8] = ((const uint4*)g_w2_bf)[l];
    }
    __syncthreads();

    // ---- MLP2 + residual: 4 m-groups x 3 n-groups (2 n-tiles each) ----
    {
        FragC acc[2][2];
        #pragma unroll
        for (int mi = 0; mi < 2; ++mi)
            #pragma unroll
            for (int j = 0; j < 2; ++j)
                wmma::fill_fragment(acc[mi][j], 0.0f);
        for (int k = 0; k < 24; ++k) {
            FragA a0, a1;
            wmma::load_matrix_sync(a0, &s_h[m0g][k * 16], 392);
            wmma::load_matrix_sync(a1, &s_h[m0g + 16][k * 16], 392);
            #pragma unroll
            for (int j = 0; j < 2; ++j) {
                FragB b;
                wmma::load_matrix_sync(b, &s_w[(k * 16) * 104 + (wn * 2 + j) * 16], 104);
                wmma::mma_sync(acc[0][j], a0, b, acc[0][j]);
                wmma::mma_sync(acc[1][j], a1, b, acc[1][j]);
            }
        }
        #pragma unroll
        for (int mi = 0; mi < 2; ++mi) {
            #pragma unroll
            for (int j = 0; j < 2; ++j) {
                int n0 = (wn * 2 + j) * 16;
                wmma::store_matrix_sync(&s_wb[warp][0][0], acc[mi][j], 20,
                                        wmma::mem_row_major);
                __syncwarp();
                float* row = s_wb[warp][r];
                size_t gi = (size_t)(tok0 + m0g + mi * 16 + r) * 96 + n0 + c0;
                float4 x0 = *(const float4*)&g_x1[gi];
                float4 x1v = *(const float4*)&g_x1[gi + 4];
                *(float4*)&out[gi] = make_float4(
                    x0.x + row[c0]     + b2[n0 + c0],
                    x0.y + row[c0 + 1] + b2[n0 + c0 + 1],
                    x0.z + row[c0 + 2] + b2[n0 + c0 + 2],
                    x0.w + row[c0 + 3] + b2[n0 + c0 + 3]);
                *(float4*)&out[gi + 4] = make_float4(
                    x1v.x + row[c0 + 4] + b2[n0 + c0 + 4],
                    x1v.y + row[c0 + 5] + b2[n0 + c0 + 5],
                    x1v.z + row[c0 + 6] + b2[n0 + c0 + 6],
                    x1v.w + row[c0 + 7] + b2[n0 + c0 + 7]);
                __syncwarp();
            }
        }
    }
}

// =======================================================================
extern "C" void kernel_launch(void* const* d_in, const int* in_sizes, int n_in,
                              void* d_out, int out_size)
{
    const float* x         = (const float*)d_in[0];
    const float* ln1_scale = (const float*)d_in[1];
    const float* ln1_bias  = (const float*)d_in[2];
    const float* qkv_w     = (const float*)d_in[3];
    const float* qkv_b     = (const float*)d_in[4];
    const float* rpbt      = (const float*)d_in[5];
    const float* proj_w    = (const float*)d_in[6];
    const float* proj_b    = (const float*)d_in[7];
    const float* ln2_scale = (const float*)d_in[8];
    const float* ln2_bias  = (const float*)d_in[9];
    const float* mlp_w1    = (const float*)d_in[10];
    const float* mlp_b1    = (const float*)d_in[11];
    const float* mlp_w2    = (const float*)d_in[12];
    const float* mlp_b2    = (const float*)d_in[13];
    float* out = (float*)d_out;

    cudaFuncSetAttribute(mega_kernel, cudaFuncAttributeMaxDynamicSharedMemorySize, MEGA_SMEM);
    cudaFuncSetAttribute(mlp_kernel,  cudaFuncAttributeMaxDynamicSharedMemorySize, MLP_SMEM);

    conv_weights<<<144, 256>>>(qkv_w, proj_w, mlp_w1, mlp_w2, rpbt);
    mega_kernel<<<NWIN, 384, MEGA_SMEM>>>(x, ln1_scale, ln1_bias, qkv_b, proj_b);
    mlp_kernel<<<TOKENS / 128, 384, MLP_SMEM>>>(ln2_scale, ln2_bias, mlp_b1, mlp_b2, out);
}

// round 8
// speedup vs baseline: 3.2969x; 1.0637x over previous
#include <cuda_runtime.h>
#include <cuda_bf16.h>
#include <mma.h>
#include <cstdint>

using namespace nvcuda;

#define BATCH   8
#define HRES    256
#define WRES    256
#define CDIM    96
#define HEADS   6
#define WS      8
#define SHIFT   4
#define NWIN    8192
#define TOKENS  524288

__device__ __align__(128) float g_x1[(size_t)TOKENS * 96];

__device__ __align__(128) __nv_bfloat16 g_qkvw_bf[96 * 288];
__device__ __align__(128) __nv_bfloat16 g_projw_bf[96 * 96];
__device__ __align__(128) __nv_bfloat16 g_w1_bf[96 * 384];
__device__ __align__(128) __nv_bfloat16 g_w2_bf[384 * 96];
__device__ __align__(128) float g_bias[HEADS * 64 * 64];

__device__ __forceinline__ int token_to_pixel(int tw) {
    int win = tw >> 6, p = tw & 63;
    int b  = win >> 10;
    int rem = win & 1023;
    int wh = rem >> 5, ww = rem & 31;
    int hh = (wh << 3) + (p >> 3);
    int wp = (ww << 3) + (p & 7);
    int sh = (hh + SHIFT) & 255;
    int sw = (wp + SHIFT) & 255;
    return (b << 16) | (sh << 8) | sw;
}

__device__ __forceinline__ float gelu_f(float v) {
    float inner = 0.7978845608028654f * (v + 0.044715f * v * v * v);
    return 0.5f * v * (1.0f + tanhf(inner));
}

typedef wmma::fragment<wmma::matrix_a, 16, 16, 16, __nv_bfloat16, wmma::row_major> FragA;
typedef wmma::fragment<wmma::matrix_b, 16, 16, 16, __nv_bfloat16, wmma::row_major> FragB;
typedef wmma::fragment<wmma::matrix_b, 16, 16, 16, __nv_bfloat16, wmma::col_major> FragBT;
typedef wmma::fragment<wmma::accumulator, 16, 16, 16, float> FragC;

__device__ __forceinline__ uint4 pack8_bf16(const float* v) {
    __nv_bfloat162 p0 = __floats2bfloat162_rn(v[0], v[1]);
    __nv_bfloat162 p1 = __floats2bfloat162_rn(v[2], v[3]);
    __nv_bfloat162 p2 = __floats2bfloat162_rn(v[4], v[5]);
    __nv_bfloat162 p3 = __floats2bfloat162_rn(v[6], v[7]);
    uint4 u;
    u.x = *(unsigned int*)&p0; u.y = *(unsigned int*)&p1;
    u.z = *(unsigned int*)&p2; u.w = *(unsigned int*)&p3;
    return u;
}

// =======================================================================
// Kernel 0: convert weights + rel-pos bias table
// =======================================================================
__global__ void conv_weights(const float* __restrict__ qkvw,
                             const float* __restrict__ projw,
                             const float* __restrict__ w1,
                             const float* __restrict__ w2,
                             const float* __restrict__ rpbt)
{
    int i = blockIdx.x * 256 + threadIdx.x;
    if (i < 96 * 288) g_qkvw_bf[i] = __float2bfloat16(qkvw[i]);
    if (i < 96 * 96)  g_projw_bf[i] = __float2bfloat16(projw[i]);
    if (i < 96 * 384) g_w1_bf[i]   = __float2bfloat16(w1[i]);
    if (i < 384 * 96) g_w2_bf[i]   = __float2bfloat16(w2[i]);
    if (i < HEADS * 4096) {
        int h = i >> 12, r = (i >> 6) & 63, j = i & 63;
        int idx = ((r >> 3) - (j >> 3) + 7) * 15 + ((r & 7) - (j & 7) + 7);
        g_bias[i] = rpbt[idx * 6 + h];
    }
}

// =======================================================================
// MEGA kernel: LN1 + QKV + attention + proj + scatter + residual
// 1 block = 1 window, 512 threads (16 warps), 202.5 KB smem
// =======================================================================
#define MEGA_SMEM 202496
__global__ __launch_bounds__(512) void mega_kernel(
    const float* __restrict__ x, const float* __restrict__ lng,
    const float* __restrict__ lnb, const float* __restrict__ qkvb,
    const float* __restrict__ projb)
{
    extern __shared__ char smem[];
    __nv_bfloat16* s_w             = (__nv_bfloat16*)smem;                     // qkvW [96][296] / projW [96][104]
    __nv_bfloat16 (*s_qkv)[296]    = (__nv_bfloat16(*)[296])(smem + 56832);    // 37888
    __nv_bfloat16 (*s_ao)[104]     = (__nv_bfloat16(*)[104])(smem + 94720);    // 13312
    float         (*s_att)[16][72] = (float(*)[16][72])(smem + 108032);        // 73728 (16 warps)
    float         (*s_wb)[16][20]  = (float(*)[16][20])(smem + 181760);        // 20480
    int*           s_reg           = (int*)(smem + 202240);                    // 256

    const int tid  = threadIdx.x;
    const int win  = blockIdx.x;
    const int tok0 = win << 6;
    const int warp = tid >> 5, lane = tid & 31;

    // stage QKV weights: 96 rows x 36 uint4, stride 296
    for (int l = tid; l < 3456; l += 512) {
        int row = l / 36, c = l % 36;
        *(uint4*)&s_w[row * 296 + c * 8] = ((const uint4*)g_qkvw_bf)[l];
    }

    const int remw = win & 1023;
    const int wh = remw >> 5, ww = remw & 31;
    const bool boundary = (wh == 31) || (ww == 31);
    if (tid < 64) {
        int hh = (wh << 3) + (tid >> 3);
        int wp = (ww << 3) + (tid & 7);
        int rh = (hh < 248) ? 0 : ((hh < 252) ? 1 : 2);
        int rw = (wp < 248) ? 0 : ((wp < 252) ? 1 : 2);
        s_reg[tid] = rh * 3 + rw;
    }

    // LN1 (warp per token)
    for (int t = warp; t < 64; t += 16) {
        int gidx = token_to_pixel(tok0 + t);
        const float* row = &x[(size_t)gidx * 96];
        float v0 = row[lane], v1 = row[lane + 32], v2 = row[lane + 64];
        float s = v0 + v1 + v2;
        float q = v0 * v0 + v1 * v1 + v2 * v2;
        #pragma unroll
        for (int o = 16; o; o >>= 1) {
            s += __shfl_xor_sync(0xffffffffu, s, o);
            q += __shfl_xor_sync(0xffffffffu, q, o);
        }
        float mu  = s * (1.0f / 96.0f);
        float var = q * (1.0f / 96.0f) - mu * mu;
        float rs  = rsqrtf(var + 1e-5f);
        s_ao[t][lane]      = __float2bfloat16((v0 - mu) * rs * lng[lane]      + lnb[lane]);
        s_ao[t][lane + 32] = __float2bfloat16((v1 - mu) * rs * lng[lane + 32] + lnb[lane + 32]);
        s_ao[t][lane + 64] = __float2bfloat16((v2 - mu) * rs * lng[lane + 64] + lnb[lane + 64]);
    }
    __syncthreads();

    const int r  = lane >> 1, c0 = (lane & 1) * 8;

    // ---- QKV GEMM: 4 m-tiles x 4 n-groups, n-tiles round-robin ----
    {
        const int mg = warp & 3, wn = warp >> 2;
        const int m0 = mg * 16;
        FragA af[6];
        #pragma unroll
        for (int k = 0; k < 6; ++k)
            wmma::load_matrix_sync(af[k], &s_ao[m0][k * 16], 104);
        for (int nt = wn; nt < 18; nt += 4) {
            FragC acc;
            wmma::fill_fragment(acc, 0.0f);
            #pragma unroll
            for (int k = 0; k < 6; ++k) {
                FragB b;
                wmma::load_matrix_sync(b, &s_w[(k * 16) * 296 + nt * 16], 296);
                wmma::mma_sync(acc, af[k], b, acc);
            }
            wmma::store_matrix_sync(&s_wb[warp][0][0], acc, 20, wmma::mem_row_major);
            __syncwarp();
            int n0 = nt * 16;
            float v[8];
            float scale = (n0 < 96) ? 0.25f : 1.0f;
            #pragma unroll
            for (int i = 0; i < 8; ++i)
                v[i] = (s_wb[warp][r][c0 + i] + qkvb[n0 + c0 + i]) * scale;
            *(uint4*)&s_qkv[m0 + r][n0 + c0] = pack8_bf16(v);
            __syncwarp();
        }
    }
    __syncthreads();

    // stage proj weights (s_w now dead) — overlaps attention phase
    for (int l = tid; l < 1152; l += 512) {
        int row = l / 12, c = l % 12;
        *(uint4*)&s_w[row * 104 + c * 8] = ((const uint4*)g_projw_bf)[l];
    }

    // ---- attention: 24 units (6 heads x 4 m-tiles) over 16 warps ----
    for (int u = warp; u < 24; u += 16) {
        const int h = u >> 2, mt = u & 3;
        const int m0 = mt * 16;
        // QK^T with rel-pos bias preloaded as C
        {
            FragA a;
            wmma::load_matrix_sync(a, &s_qkv[m0][h * 16], 296);
            #pragma unroll
            for (int c = 0; c < 4; ++c) {
                FragC acc;
                wmma::load_matrix_sync(acc, &g_bias[(h << 12) + m0 * 64 + c * 16], 64,
                                       wmma::mem_row_major);
                FragBT bt;
                wmma::load_matrix_sync(bt, &s_qkv[c * 16][96 + h * 16], 296);
                wmma::mma_sync(acc, a, bt, acc);
                wmma::store_matrix_sync(&s_att[warp][0][c * 16], acc, 72, wmma::mem_row_major);
            }
        }
        __syncwarp();
        // softmax: bf16 probs aliased onto the fp32 logit buffer.
        // bf16 row rr occupies fp32 row rr/2 (already consumed); the
        // shfl reductions are warp barriers between the reads and writes.
        __nv_bfloat16 (*pw)[72] = (__nv_bfloat16(*)[72])&s_att[warp][0][0];
        for (int rr = 0; rr < 16; ++rr) {
            float a0 = s_att[warp][rr][lane];
            float a1 = s_att[warp][rr][lane + 32];
            if (boundary) {
                int ri = s_reg[m0 + rr];
                if (ri != s_reg[lane])      a0 -= 100.0f;
                if (ri != s_reg[lane + 32]) a1 -= 100.0f;
            }
            float m = fmaxf(a0, a1);
            #pragma unroll
            for (int o = 16; o; o >>= 1) m = fmaxf(m, __shfl_xor_sync(0xffffffffu, m, o));
            float e0 = __expf(a0 - m), e1 = __expf(a1 - m);
            float s = e0 + e1;
            #pragma unroll
            for (int o = 16; o; o >>= 1) s += __shfl_xor_sync(0xffffffffu, s, o);
            float inv = 1.0f / s;
            pw[rr][lane]      = __float2bfloat16(e0 * inv);
            pw[rr][lane + 32] = __float2bfloat16(e1 * inv);
        }
        __syncwarp();
        // o = P @ V  (result staged via s_wb)
        {
            FragC acc;
            wmma::fill_fragment(acc, 0.0f);
            #pragma unroll
            for (int kc = 0; kc < 4; ++kc) {
                FragA ap;
                wmma::load_matrix_sync(ap, &pw[0][kc * 16], 72);
                FragB bv;
                wmma::load_matrix_sync(bv, &s_qkv[kc * 16][192 + h * 16], 296);
                wmma::mma_sync(acc, ap, bv, acc);
            }
            wmma::store_matrix_sync(&s_wb[warp][0][0], acc, 20, wmma::mem_row_major);
            __syncwarp();
            float v[8];
            #pragma unroll
            for (int i = 0; i < 8; ++i) v[i] = s_wb[warp][r][c0 + i];
            *(uint4*)&s_ao[m0 + r][h * 16 + c0] = pack8_bf16(v);
        }
        __syncwarp();
    }
    __syncthreads();

    // ---- proj + scatter + residual: 24 jobs over 16 warps ----
    for (int j = warp; j < 24; j += 16) {
        const int mt = j & 3, nt = j >> 2;
        const int m0 = mt * 16;
        FragC acc;
        wmma::fill_fragment(acc, 0.0f);
        #pragma unroll
        for (int k = 0; k < 6; ++k) {
            FragA a;
            wmma::load_matrix_sync(a, &s_ao[m0][k * 16], 104);
            FragB b;
            wmma::load_matrix_sync(b, &s_w[(k * 16) * 104 + nt * 16], 104);
            wmma::mma_sync(acc, a, b, acc);
        }
        wmma::store_matrix_sync(&s_wb[warp][0][0], acc, 20, wmma::mem_row_major);
        __syncwarp();
        int n0 = nt * 16;
        size_t gi = (size_t)token_to_pixel(tok0 + m0 + r) * 96 + n0 + c0;
        float4 x0 = *(const float4*)&x[gi];
        float4 x1v = *(const float4*)&x[gi + 4];
        float* row = s_wb[warp][r];
        *(float4*)&g_x1[gi] = make_float4(
            x0.x + row[c0]     + projb[n0 + c0],
            x0.y + row[c0 + 1] + projb[n0 + c0 + 1],
            x0.z + row[c0 + 2] + projb[n0 + c0 + 2],
            x0.w + row[c0 + 3] + projb[n0 + c0 + 3]);
        *(float4*)&g_x1[gi + 4] = make_float4(
            x1v.x + row[c0 + 4] + projb[n0 + c0 + 4],
            x1v.y + row[c0 + 5] + projb[n0 + c0 + 5],
            x1v.z + row[c0 + 6] + projb[n0 + c0 + 6],
            x1v.w + row[c0 + 7] + projb[n0 + c0 + 7]);
        __syncwarp();
    }
}

// =======================================================================
// Kernel 2: LN2 + MLP1 + gelu + MLP2 + residual. 128 tok/block, 512 thr.
// =======================================================================
#define MLP_SMEM 227328
__global__ __launch_bounds__(512) void mlp_kernel(
    const float* __restrict__ lng, const float* __restrict__ lnb,
    const float* __restrict__ b1, const float* __restrict__ b2,
    float* __restrict__ out)
{
    extern __shared__ char smem[];
    __nv_bfloat16* s_w            = (__nv_bfloat16*)smem;                      // W1 [96][392] / W2 [384][104]
    __nv_bfloat16 (*s_a)[104]     = (__nv_bfloat16(*)[104])(smem + 79872);     // 26624
    __nv_bfloat16 (*s_h)[392]     = (__nv_bfloat16(*)[392])(smem + 106496);    // 100352
    float         (*s_wb)[16][20] = (float(*)[16][20])(smem + 206848);         // 20480

    const int tid  = threadIdx.x;
    const int tok0 = blockIdx.x * 128;
    const int warp = tid >> 5, lane = tid & 31;

    // stage W1: 96 rows x 48 uint4, stride 392
    for (int l = tid; l < 4608; l += 512) {
        int row = l / 48, c = l % 48;
        *(uint4*)&s_w[row * 392 + c * 8] = ((const uint4*)g_w1_bf)[l];
    }

    for (int t = warp; t < 128; t += 16) {
        const float* row = &g_x1[(size_t)(tok0 + t) * 96];
        float v0 = row[lane], v1 = row[lane + 32], v2 = row[lane + 64];
        float s = v0 + v1 + v2;
        float q = v0 * v0 + v1 * v1 + v2 * v2;
        #pragma unroll
        for (int o = 16; o; o >>= 1) {
            s += __shfl_xor_sync(0xffffffffu, s, o);
            q += __shfl_xor_sync(0xffffffffu, q, o);
        }
        float mu  = s * (1.0f / 96.0f);
        float var = q * (1.0f / 96.0f) - mu * mu;
        float rs  = rsqrtf(var + 1e-5f);
        s_a[t][lane]      = __float2bfloat16((v0 - mu) * rs * lng[lane]      + lnb[lane]);
        s_a[t][lane + 32] = __float2bfloat16((v1 - mu) * rs * lng[lane + 32] + lnb[lane + 32]);
        s_a[t][lane + 64] = __float2bfloat16((v2 - mu) * rs * lng[lane + 64] + lnb[lane + 64]);
    }
    __syncthreads();

    const int r  = lane >> 1, c0 = (lane & 1) * 8;

    // ---- MLP1 + gelu -> s_h : 4 m-groups(32) x 4 n-groups (6 tiles each) ----
    {
        const int mg = warp & 3, wn = warp >> 2;
        const int m0g = mg * 32;
        FragA af[2][6];
        #pragma unroll
        for (int mi = 0; mi < 2; ++mi)
            #pragma unroll
            for (int k = 0; k < 6; ++k)
                wmma::load_matrix_sync(af[mi][k], &s_a[m0g + mi * 16][k * 16], 104);

        for (int nt = wn; nt < 24; nt += 4) {
            FragC acc0, acc1;
            wmma::fill_fragment(acc0, 0.0f);
            wmma::fill_fragment(acc1, 0.0f);
            #pragma unroll
            for (int k = 0; k < 6; ++k) {
                FragB b;
                wmma::load_matrix_sync(b, &s_w[(k * 16) * 392 + nt * 16], 392);
                wmma::mma_sync(acc0, af[0][k], b, acc0);
                wmma::mma_sync(acc1, af[1][k], b, acc1);
            }
            int n0 = nt * 16;
            #pragma unroll
            for (int mi = 0; mi < 2; ++mi) {
                wmma::store_matrix_sync(&s_wb[warp][0][0], mi ? acc1 : acc0, 20,
                                        wmma::mem_row_major);
                __syncwarp();
                float v[8];
                #pragma unroll
                for (int i = 0; i < 8; ++i)
                    v[i] = gelu_f(s_wb[warp][r][c0 + i] + b1[n0 + c0 + i]);
                *(uint4*)&s_h[m0g + mi * 16 + r][n0 + c0] = pack8_bf16(v);
                __syncwarp();
            }
        }
    }
    __syncthreads();

    // stage W2: 384 rows x 12 uint4, stride 104
    for (int l = tid; l < 4608; l += 512) {
        int row = l / 12, c = l % 12;
        *(uint4*)&s_w[row * 104 + c * 8] = ((const uint4*)g_w2_bf)[l];
    }
    __syncthreads();

    // ---- MLP2 + residual: 8 m-tiles x 2 n-groups (3 tiles each) ----
    {
        const int mt = warp & 7, wn2 = warp >> 3;
        const int m0 = mt * 16;
        FragC acc[3];
        #pragma unroll
        for (int c = 0; c < 3; ++c) wmma::fill_fragment(acc[c], 0.0f);
        for (int k = 0; k < 24; ++k) {
            FragA a;
            wmma::load_matrix_sync(a, &s_h[m0][k * 16], 392);
            #pragma unroll
            for (int c = 0; c < 3; ++c) {
                FragB b;
                wmma::load_matrix_sync(b, &s_w[(k * 16) * 104 + (wn2 * 3 + c) * 16], 104);
                wmma::mma_sync(acc[c], a, b, acc[c]);
            }
        }
        #pragma unroll
        for (int c = 0; c < 3; ++c) {
            int n0 = (wn2 * 3 + c) * 16;
            wmma::store_matrix_sync(&s_wb[warp][0][0], acc[c], 20, wmma::mem_row_major);
            __syncwarp();
            float* row = s_wb[warp][r];
            size_t gi = (size_t)(tok0 + m0 + r) * 96 + n0 + c0;
            float4 x0 = *(const float4*)&g_x1[gi];
            float4 x1v = *(const float4*)&g_x1[gi + 4];
            *(float4*)&out[gi] = make_float4(
                x0.x + row[c0]     + b2[n0 + c0],
                x0.y + row[c0 + 1] + b2[n0 + c0 + 1],
                x0.z + row[c0 + 2] + b2[n0 + c0 + 2],
                x0.w + row[c0 + 3] + b2[n0 + c0 + 3]);
            *(float4*)&out[gi + 4] = make_float4(
                x1v.x + row[c0 + 4] + b2[n0 + c0 + 4],
                x1v.y + row[c0 + 5] + b2[n0 + c0 + 5],
                x1v.z + row[c0 + 6] + b2[n0 + c0 + 6],
                x1v.w + row[c0 + 7] + b2[n0 + c0 + 7]);
            __syncwarp();
        }
    }
}

// =======================================================================
extern "C" void kernel_launch(void* const* d_in, const int* in_sizes, int n_in,
                              void* d_out, int out_size)
{
    const float* x         = (const float*)d_in[0];
    const float* ln1_scale = (const float*)d_in[1];
    const float* ln1_bias  = (const float*)d_in[2];
    const float* qkv_w     = (const float*)d_in[3];
    const float* qkv_b     = (const float*)d_in[4];
    const float* rpbt      = (const float*)d_in[5];
    const float* proj_w    = (const float*)d_in[6];
    const float* proj_b    = (const float*)d_in[7];
    const float* ln2_scale = (const float*)d_in[8];
    const float* ln2_bias  = (const float*)d_in[9];
    const float* mlp_w1    = (const float*)d_in[10];
    const float* mlp_b1    = (const float*)d_in[11];
    const float* mlp_w2    = (const float*)d_in[12];
    const float* mlp_b2    = (const float*)d_in[13];
    float* out = (float*)d_out;

    cudaFuncSetAttribute(mega_kernel, cudaFuncAttributeMaxDynamicSharedMemorySize, MEGA_SMEM);
    cudaFuncSetAttribute(mlp_kernel,  cudaFuncAttributeMaxDynamicSharedMemorySize, MLP_SMEM);

    conv_weights<<<144, 256>>>(qkv_w, proj_w, mlp_w1, mlp_w2, rpbt);
    mega_kernel<<<NWIN, 512, MEGA_SMEM>>>(x, ln1_scale, ln1_bias, qkv_b, proj_b);
    mlp_kernel<<<TOKENS / 128, 512, MLP_SMEM>>>(ln2_scale, ln2_bias, mlp_b1, mlp_b2, out);
}